// round 1
// baseline (speedup 1.0000x reference)
#include <cuda_runtime.h>
#include <math.h>

// Problem constants
#define Bdim 8
#define Nseq 4096
#define Dmod 512
#define Hh   8
#define Rr   256
#define DP   64
#define BH   64          // Bdim*Hh
#define MT   32768       // Bdim*Nseq

// Scratch (module-static device memory; allowed per harness rules)
__device__ float g_q [(size_t)BH * Nseq * DP];
__device__ float g_k [(size_t)BH * Nseq * DP];
__device__ float g_v [(size_t)BH * Nseq * DP];
__device__ float g_kp[(size_t)BH * Rr * DP];
__device__ float g_vp[(size_t)BH * Rr * DP];
__device__ float g_cat[(size_t)MT * Dmod];

// ---------------------------------------------------------------------------
// Kernel 1: QKV projection.  C(32768x512) = x(32768x512) @ w(512x512),
// output scattered to (b,h,n,d) layout. grid = (256, 4, 3), block = 256.
// ---------------------------------------------------------------------------
__global__ __launch_bounds__(256) void qkv_kernel(
    const float* __restrict__ x,
    const float* __restrict__ wq,
    const float* __restrict__ wk,
    const float* __restrict__ wv)
{
    const float* w   = (blockIdx.z == 0) ? wq : (blockIdx.z == 1) ? wk : wv;
    float*       out = (blockIdx.z == 0) ? g_q : (blockIdx.z == 1) ? g_k : g_v;

    __shared__ float As[128 * 20];   // [m][k], padded stride 20
    __shared__ float Bs[16 * 128];   // [k][n]

    const int t = threadIdx.x;
    const int rowBase = blockIdx.x * 128;
    const int colBase = blockIdx.y * 128;
    const int ty = t >> 4, tx = t & 15;

    float acc[8][8];
#pragma unroll
    for (int i = 0; i < 8; i++)
#pragma unroll
        for (int j = 0; j < 8; j++) acc[i][j] = 0.f;

    for (int k0 = 0; k0 < Dmod; k0 += 16) {
#pragma unroll
        for (int u = 0; u < 2; u++) {
            int v = t * 2 + u;
            int r = v >> 2, kv = (v & 3) * 4;
            float4 a = *(const float4*)(x + (size_t)(rowBase + r) * Dmod + k0 + kv);
            As[r * 20 + kv + 0] = a.x;
            As[r * 20 + kv + 1] = a.y;
            As[r * 20 + kv + 2] = a.z;
            As[r * 20 + kv + 3] = a.w;
        }
#pragma unroll
        for (int u = 0; u < 2; u++) {
            int v = t + u * 256;
            int kr = v >> 5, nv = (v & 31) * 4;
            *(float4*)(Bs + kr * 128 + nv) =
                *(const float4*)(w + (size_t)(k0 + kr) * Dmod + colBase + nv);
        }
        __syncthreads();
#pragma unroll
        for (int k = 0; k < 16; k++) {
            float a[8], b[8];
#pragma unroll
            for (int i = 0; i < 8; i++) a[i] = As[(ty * 8 + i) * 20 + k];
            float4 b0 = *(float4*)(Bs + k * 128 + tx * 8);
            float4 b1 = *(float4*)(Bs + k * 128 + tx * 8 + 4);
            b[0] = b0.x; b[1] = b0.y; b[2] = b0.z; b[3] = b0.w;
            b[4] = b1.x; b[5] = b1.y; b[6] = b1.z; b[7] = b1.w;
#pragma unroll
            for (int i = 0; i < 8; i++)
#pragma unroll
                for (int j = 0; j < 8; j++) acc[i][j] = fmaf(a[i], b[j], acc[i][j]);
        }
        __syncthreads();
    }

    // Scatter to (b,h,n,d)
#pragma unroll
    for (int i = 0; i < 8; i++) {
        int row = rowBase + ty * 8 + i;
        int bb = row >> 12, n = row & 4095;
#pragma unroll
        for (int jj = 0; jj < 2; jj++) {
            int col = colBase + tx * 8 + jj * 4;
            int h = col >> 6, d = col & 63;
            float4 v = make_float4(acc[i][jj * 4 + 0], acc[i][jj * 4 + 1],
                                   acc[i][jj * 4 + 2], acc[i][jj * 4 + 3]);
            *(float4*)(out + ((size_t)(bb * Hh + h) * Nseq + n) * DP + d) = v;
        }
    }
}

// ---------------------------------------------------------------------------
// Kernel 2: low-rank projections.  kp[r,d] = sum_n E[h,n,r] * k[b,h,n,d]
// One block computes the full (256 x 64) output for one (b,h) and one of
// {K->kp via E, V->vp via F}.  grid = (64, 2), block = 256.
// ---------------------------------------------------------------------------
__global__ __launch_bounds__(256) void proj_kernel(
    const float* __restrict__ E, const float* __restrict__ F)
{
    const int bh = blockIdx.x;
    const int h  = bh & 7;
    const float* A  = ((blockIdx.y == 0) ? E : F) + (size_t)h * Nseq * Rr;
    const float* Bm = ((blockIdx.y == 0) ? g_k : g_v) + (size_t)bh * Nseq * DP;
    float*       out = ((blockIdx.y == 0) ? g_kp : g_vp) + (size_t)bh * Rr * DP;

    __shared__ float Es[16 * 256];   // [kn][r]
    __shared__ float Ks[16 * 64];    // [kn][d]

    const int t = threadIdx.x;
    const int tr = t >> 3, td = t & 7;   // tr: 0..31 (r groups of 8), td: 0..7 (d groups of 8)

    float acc[8][8];
#pragma unroll
    for (int i = 0; i < 8; i++)
#pragma unroll
        for (int j = 0; j < 8; j++) acc[i][j] = 0.f;

    for (int n0 = 0; n0 < Nseq; n0 += 16) {
#pragma unroll
        for (int u = 0; u < 4; u++) {
            int v = t + u * 256;
            int kn = v >> 6, rv = (v & 63) * 4;
            *(float4*)(Es + kn * 256 + rv) =
                *(const float4*)(A + (size_t)(n0 + kn) * Rr + rv);
        }
        {
            int kn = t >> 4, dv = (t & 15) * 4;
            *(float4*)(Ks + kn * 64 + dv) =
                *(const float4*)(Bm + (size_t)(n0 + kn) * DP + dv);
        }
        __syncthreads();
#pragma unroll
        for (int k = 0; k < 16; k++) {
            float a[8], b[8];
            float4 a0 = *(float4*)(Es + k * 256 + tr * 8);
            float4 a1 = *(float4*)(Es + k * 256 + tr * 8 + 4);
            a[0] = a0.x; a[1] = a0.y; a[2] = a0.z; a[3] = a0.w;
            a[4] = a1.x; a[5] = a1.y; a[6] = a1.z; a[7] = a1.w;
            float4 b0 = *(float4*)(Ks + k * 64 + td * 8);
            float4 b1 = *(float4*)(Ks + k * 64 + td * 8 + 4);
            b[0] = b0.x; b[1] = b0.y; b[2] = b0.z; b[3] = b0.w;
            b[4] = b1.x; b[5] = b1.y; b[6] = b1.z; b[7] = b1.w;
#pragma unroll
            for (int i = 0; i < 8; i++)
#pragma unroll
                for (int j = 0; j < 8; j++) acc[i][j] = fmaf(a[i], b[j], acc[i][j]);
        }
        __syncthreads();
    }

#pragma unroll
    for (int i = 0; i < 8; i++) {
        int r = tr * 8 + i;
        *(float4*)(out + (size_t)r * DP + td * 8) =
            make_float4(acc[i][0], acc[i][1], acc[i][2], acc[i][3]);
        *(float4*)(out + (size_t)r * DP + td * 8 + 4) =
            make_float4(acc[i][4], acc[i][5], acc[i][6], acc[i][7]);
    }
}

// ---------------------------------------------------------------------------
// Kernel 3: fused attention. Per block: one (b,h) and one 64-row Q tile.
// scores = Q @ kp^T * 0.125 -> softmax (rows warp-owned) -> out = P @ vp.
// Writes directly into concat layout (b, n, h*64+d).
// grid = (64, 64), block = 256, dynamic smem = 147456 B.
// smem layout (floats): kps [0,16384) as [d][r]; Qs [16384,20480) as [m][d];
// vps [20480,36864) as [r][d]; attn aliases [0,16448) as [m][257] (kps/Qs dead).
// ---------------------------------------------------------------------------
__global__ __launch_bounds__(256) void attn_kernel()
{
    extern __shared__ float sm[];
    float* kps  = sm;            // [64][256]  (d-major)
    float* Qs   = sm + 16384;    // [64][64]
    float* vps  = sm + 20480;    // [256][64]
    float* attn = sm;            // [64][257]  aliases kps + start of Qs

    const int t = threadIdx.x;
    const int bh = blockIdx.x, tile = blockIdx.y;
    const float* kp = g_kp + (size_t)bh * Rr * DP;
    const float* vp = g_vp + (size_t)bh * Rr * DP;
    const float* q  = g_q  + (size_t)bh * Nseq * DP + (size_t)tile * 64 * DP;

    // kp load + transpose: thread t owns r = t
#pragma unroll
    for (int d0 = 0; d0 < 16; d0++) {
        float4 v = *(const float4*)(kp + (size_t)t * DP + d0 * 4);
        kps[(d0 * 4 + 0) * 256 + t] = v.x;
        kps[(d0 * 4 + 1) * 256 + t] = v.y;
        kps[(d0 * 4 + 2) * 256 + t] = v.z;
        kps[(d0 * 4 + 3) * 256 + t] = v.w;
    }
#pragma unroll
    for (int u = 0; u < 16; u++) {
        int v4 = t + u * 256;
        *(float4*)(vps + v4 * 4) = *(const float4*)(vp + v4 * 4);
    }
#pragma unroll
    for (int u = 0; u < 4; u++) {
        int v4 = t + u * 256;
        *(float4*)(Qs + v4 * 4) = *(const float4*)(q + v4 * 4);
    }
    __syncthreads();

    // GEMM1: scores[64][256]; warp trow owns rows trow*8..+7, lane owns r=lane*8..+7
    const int trow = t >> 5, lane = t & 31;
    float s[8][8];
#pragma unroll
    for (int i = 0; i < 8; i++)
#pragma unroll
        for (int j = 0; j < 8; j++) s[i][j] = 0.f;

#pragma unroll 16
    for (int kd = 0; kd < 64; kd++) {
        float a[8], b[8];
#pragma unroll
        for (int i = 0; i < 8; i++) a[i] = Qs[(trow * 8 + i) * 64 + kd];
        float4 b0 = *(float4*)(kps + kd * 256 + lane * 8);
        float4 b1 = *(float4*)(kps + kd * 256 + lane * 8 + 4);
        b[0] = b0.x; b[1] = b0.y; b[2] = b0.z; b[3] = b0.w;
        b[4] = b1.x; b[5] = b1.y; b[6] = b1.z; b[7] = b1.w;
#pragma unroll
        for (int i = 0; i < 8; i++)
#pragma unroll
            for (int j = 0; j < 8; j++) s[i][j] = fmaf(a[i], b[j], s[i][j]);
    }

    // softmax per row (scale 1/sqrt(64) = 0.125 applied inside exp)
#pragma unroll
    for (int i = 0; i < 8; i++) {
        float mx = s[i][0];
#pragma unroll
        for (int j = 1; j < 8; j++) mx = fmaxf(mx, s[i][j]);
        for (int o = 16; o > 0; o >>= 1)
            mx = fmaxf(mx, __shfl_xor_sync(0xffffffffu, mx, o));
        float sum = 0.f;
#pragma unroll
        for (int j = 0; j < 8; j++) {
            s[i][j] = __expf((s[i][j] - mx) * 0.125f);
            sum += s[i][j];
        }
        for (int o = 16; o > 0; o >>= 1)
            sum += __shfl_xor_sync(0xffffffffu, sum, o);
        float inv = 1.f / sum;
#pragma unroll
        for (int j = 0; j < 8; j++) s[i][j] *= inv;
    }

    __syncthreads();   // all kps/Qs reads done before aliasing with attn
#pragma unroll
    for (int i = 0; i < 8; i++)
#pragma unroll
        for (int j = 0; j < 8; j++)
            attn[(trow * 8 + i) * 257 + lane * 8 + j] = s[i][j];
    __syncthreads();

    // GEMM2: out[64][64] = attn @ vps. thread: 2 rows x 8 cols.
    const int trr = t >> 3, tq = t & 7;
    float o[2][8];
#pragma unroll
    for (int i = 0; i < 2; i++)
#pragma unroll
        for (int j = 0; j < 8; j++) o[i][j] = 0.f;

#pragma unroll 8
    for (int r = 0; r < Rr; r++) {
        float a0 = attn[(trr * 2 + 0) * 257 + r];
        float a1 = attn[(trr * 2 + 1) * 257 + r];
        float bb[8];
        float4 b0 = *(float4*)(vps + r * 64 + tq * 8);
        float4 b1 = *(float4*)(vps + r * 64 + tq * 8 + 4);
        bb[0] = b0.x; bb[1] = b0.y; bb[2] = b0.z; bb[3] = b0.w;
        bb[4] = b1.x; bb[5] = b1.y; bb[6] = b1.z; bb[7] = b1.w;
#pragma unroll
        for (int j = 0; j < 8; j++) {
            o[0][j] = fmaf(a0, bb[j], o[0][j]);
            o[1][j] = fmaf(a1, bb[j], o[1][j]);
        }
    }

    const int b = bh >> 3, h = bh & 7;
    const size_t base = ((size_t)(b * Nseq) + tile * 64) * Dmod + h * DP;
#pragma unroll
    for (int i = 0; i < 2; i++) {
        int row = trr * 2 + i;
        *(float4*)(g_cat + base + (size_t)row * Dmod + tq * 8) =
            make_float4(o[i][0], o[i][1], o[i][2], o[i][3]);
        *(float4*)(g_cat + base + (size_t)row * Dmod + tq * 8 + 4) =
            make_float4(o[i][4], o[i][5], o[i][6], o[i][7]);
    }
}

// ---------------------------------------------------------------------------
// Kernel 4: output dense.  out = g_cat(32768x512) @ w(512x512) + bias.
// grid = (256, 4), block = 256.
// ---------------------------------------------------------------------------
__global__ __launch_bounds__(256) void dense_kernel(
    const float* __restrict__ w, const float* __restrict__ bias,
    float* __restrict__ out)
{
    __shared__ float As[128 * 20];
    __shared__ float Bs[16 * 128];

    const int t = threadIdx.x;
    const int rowBase = blockIdx.x * 128;
    const int colBase = blockIdx.y * 128;
    const int ty = t >> 4, tx = t & 15;

    float acc[8][8];
#pragma unroll
    for (int i = 0; i < 8; i++)
#pragma unroll
        for (int j = 0; j < 8; j++) acc[i][j] = 0.f;

    for (int k0 = 0; k0 < Dmod; k0 += 16) {
#pragma unroll
        for (int u = 0; u < 2; u++) {
            int v = t * 2 + u;
            int r = v >> 2, kv = (v & 3) * 4;
            float4 a = *(const float4*)(g_cat + (size_t)(rowBase + r) * Dmod + k0 + kv);
            As[r * 20 + kv + 0] = a.x;
            As[r * 20 + kv + 1] = a.y;
            As[r * 20 + kv + 2] = a.z;
            As[r * 20 + kv + 3] = a.w;
        }
#pragma unroll
        for (int u = 0; u < 2; u++) {
            int v = t + u * 256;
            int kr = v >> 5, nv = (v & 31) * 4;
            *(float4*)(Bs + kr * 128 + nv) =
                *(const float4*)(w + (size_t)(k0 + kr) * Dmod + colBase + nv);
        }
        __syncthreads();
#pragma unroll
        for (int k = 0; k < 16; k++) {
            float a[8], b[8];
#pragma unroll
            for (int i = 0; i < 8; i++) a[i] = As[(ty * 8 + i) * 20 + k];
            float4 b0 = *(float4*)(Bs + k * 128 + tx * 8);
            float4 b1 = *(float4*)(Bs + k * 128 + tx * 8 + 4);
            b[0] = b0.x; b[1] = b0.y; b[2] = b0.z; b[3] = b0.w;
            b[4] = b1.x; b[5] = b1.y; b[6] = b1.z; b[7] = b1.w;
#pragma unroll
            for (int i = 0; i < 8; i++)
#pragma unroll
                for (int j = 0; j < 8; j++) acc[i][j] = fmaf(a[i], b[j], acc[i][j]);
        }
        __syncthreads();
    }

#pragma unroll
    for (int i = 0; i < 8; i++) {
        int row = rowBase + ty * 8 + i;
#pragma unroll
        for (int jj = 0; jj < 2; jj++) {
            int col = colBase + tx * 8 + jj * 4;
            float4 bi = *(const float4*)(bias + col);
            float4 v = make_float4(acc[i][jj * 4 + 0] + bi.x,
                                   acc[i][jj * 4 + 1] + bi.y,
                                   acc[i][jj * 4 + 2] + bi.z,
                                   acc[i][jj * 4 + 3] + bi.w);
            *(float4*)(out + (size_t)row * Dmod + col) = v;
        }
    }
}

// ---------------------------------------------------------------------------
extern "C" void kernel_launch(void* const* d_in, const int* in_sizes, int n_in,
                              void* d_out, int out_size)
{
    const float* x  = (const float*)d_in[0];
    const float* wq = (const float*)d_in[1];
    const float* wk = (const float*)d_in[2];
    const float* wv = (const float*)d_in[3];
    const float* E  = (const float*)d_in[4];
    const float* F  = (const float*)d_in[5];
    const float* wd = (const float*)d_in[6];
    const float* bd = (const float*)d_in[7];
    float* out = (float*)d_out;

    qkv_kernel<<<dim3(MT / 128, Dmod / 128, 3), 256>>>(x, wq, wk, wv);
    proj_kernel<<<dim3(BH, 2), 256>>>(E, F);

    cudaFuncSetAttribute(attn_kernel,
                         cudaFuncAttributeMaxDynamicSharedMemorySize, 147456);
    attn_kernel<<<dim3(BH, Nseq / 64), 256, 147456>>>();

    dense_kernel<<<dim3(MT / 128, Dmod / 128), 256>>>(wd, bd, out);
}

// round 3
// speedup vs baseline: 1.5645x; 1.5645x over previous
#include <cuda_runtime.h>
#include <cuda_bf16.h>
#include <stdint.h>
#include <math.h>

// Problem constants
#define Bdim 8
#define Nseq 4096
#define Dmod 512
#define Hh   8
#define Rr   256
#define DP   64
#define BH   64          // Bdim*Hh
#define MT   32768       // Bdim*Nseq

// ---------------------------------------------------------------------------
// Scratch
// ---------------------------------------------------------------------------
__device__ float g_q [(size_t)BH * Nseq * DP];
__device__ float g_k [(size_t)BH * Nseq * DP];
__device__ float g_v [(size_t)BH * Nseq * DP];
__device__ float g_kp[(size_t)BH * Rr * DP];
__device__ float g_vp[(size_t)BH * Rr * DP];
__device__ float g_cat[(size_t)MT * Dmod];

__device__ __nv_bfloat16 g_xhi[(size_t)MT * Dmod];
__device__ __nv_bfloat16 g_xlo[(size_t)MT * Dmod];
__device__ __nv_bfloat16 g_chi[(size_t)MT * Dmod];
__device__ __nv_bfloat16 g_clo[(size_t)MT * Dmod];
__device__ __nv_bfloat16 g_whi[4 * Dmod * Dmod];   // [z][n][k] (transposed)
__device__ __nv_bfloat16 g_wlo[4 * Dmod * Dmod];

// ---------------------------------------------------------------------------
// PTX helpers (compute_103-safe: cp.async / ldmatrix / mma.sync only)
// ---------------------------------------------------------------------------
__device__ __forceinline__ uint32_t smem_u32(const void* p) {
    uint32_t a;
    asm("{ .reg .u64 t; cvta.to.shared.u64 t, %1; cvt.u32.u64 %0, t; }" : "=r"(a) : "l"(p));
    return a;
}
__device__ __forceinline__ void cpa16(uint32_t dst, const void* src) {
    asm volatile("cp.async.cg.shared.global [%0], [%1], 16;" :: "r"(dst), "l"(src));
}
__device__ __forceinline__ void ldsm4(uint32_t& r0, uint32_t& r1, uint32_t& r2,
                                      uint32_t& r3, uint32_t addr) {
    asm volatile("ldmatrix.sync.aligned.m8n8.x4.shared.b16 {%0,%1,%2,%3}, [%4];"
                 : "=r"(r0), "=r"(r1), "=r"(r2), "=r"(r3) : "r"(addr));
}
__device__ __forceinline__ void mma16816(float* c, uint32_t a0, uint32_t a1,
                                         uint32_t a2, uint32_t a3,
                                         uint32_t b0, uint32_t b1) {
    asm volatile(
        "mma.sync.aligned.m16n8k16.row.col.f32.bf16.bf16.f32 "
        "{%0,%1,%2,%3}, {%4,%5,%6,%7}, {%8,%9}, {%0,%1,%2,%3};"
        : "+f"(c[0]), "+f"(c[1]), "+f"(c[2]), "+f"(c[3])
        : "r"(a0), "r"(a1), "r"(a2), "r"(a3), "r"(b0), "r"(b1));
}

// ---------------------------------------------------------------------------
// split kernels: fp32 -> (hi, lo) bf16
// ---------------------------------------------------------------------------
__global__ __launch_bounds__(256) void split_kernel(
    const float* __restrict__ in, __nv_bfloat16* __restrict__ hi,
    __nv_bfloat16* __restrict__ lo)
{
    size_t i = ((size_t)blockIdx.x * 256 + threadIdx.x) * 4;
    float4 v = *(const float4*)(in + i);
    __nv_bfloat16 h0 = __float2bfloat16(v.x), h1 = __float2bfloat16(v.y);
    __nv_bfloat16 h2 = __float2bfloat16(v.z), h3 = __float2bfloat16(v.w);
    __nv_bfloat16 l0 = __float2bfloat16(v.x - __bfloat162float(h0));
    __nv_bfloat16 l1 = __float2bfloat16(v.y - __bfloat162float(h1));
    __nv_bfloat16 l2 = __float2bfloat16(v.z - __bfloat162float(h2));
    __nv_bfloat16 l3 = __float2bfloat16(v.w - __bfloat162float(h3));
    *(__nv_bfloat162*)(hi + i)     = __nv_bfloat162(h0, h1);
    *(__nv_bfloat162*)(hi + i + 2) = __nv_bfloat162(h2, h3);
    *(__nv_bfloat162*)(lo + i)     = __nv_bfloat162(l0, l1);
    *(__nv_bfloat162*)(lo + i + 2) = __nv_bfloat162(l2, l3);
}

// transpose + split weights: g_w{hi,lo}[z][n][k] = split(w_z[k][n])
__global__ __launch_bounds__(256) void convw_kernel(
    const float* __restrict__ wq, const float* __restrict__ wk,
    const float* __restrict__ wv, const float* __restrict__ wd)
{
    const int z = blockIdx.z;
    const float* w = (z == 0) ? wq : (z == 1) ? wk : (z == 2) ? wv : wd;
    __shared__ float tile[32][33];
    const int k0 = blockIdx.x * 32, n0 = blockIdx.y * 32;
    const int tx = threadIdx.x, ty = threadIdx.y;   // block (32, 8)
#pragma unroll
    for (int i = 0; i < 4; i++)
        tile[ty + i * 8][tx] = w[(size_t)(k0 + ty + i * 8) * Dmod + n0 + tx];
    __syncthreads();
#pragma unroll
    for (int i = 0; i < 4; i++) {
        float x = tile[tx][ty + i * 8];
        __nv_bfloat16 h = __float2bfloat16(x);
        size_t o = (size_t)z * Dmod * Dmod + (size_t)(n0 + ty + i * 8) * Dmod + k0 + tx;
        g_whi[o] = h;
        g_wlo[o] = __float2bfloat16(x - __bfloat162float(h));
    }
}

// ---------------------------------------------------------------------------
// mma.sync split-bf16 GEMM: C(128x128 tile) = A(Mx512) @ W(512x512)
// mode 0: qkv (z = blockIdx.z; scatter epilogue to bhnd)
// mode 1: dense (z = 3; row-major epilogue + bias -> dOut)
// block 256 (8 warps = 4m x 2n, warp tile 32x64), K chunk 32, double buffer.
// smem stage (bytes): Ahi@0, Alo@10240, Bhi@20480, Blo@30720; rows padded to
// 80 B (40 bf16) for conflict-free ldmatrix. Stage stride 40960; total 81920.
// ---------------------------------------------------------------------------
__device__ __forceinline__ void issue_chunk(
    const __nv_bfloat16* __restrict__ Ahi, const __nv_bfloat16* __restrict__ Alo,
    const __nv_bfloat16* __restrict__ Bhi, const __nv_bfloat16* __restrict__ Blo,
    uint32_t sb, int stage, int c, int t, int rowBase, int colBase)
{
    const int k0 = c * 32;
#pragma unroll
    for (int u = 0; u < 2; u++) {
        int id = t + u * 256;
        int row = id >> 2, k8 = id & 3;
        size_t gA = (size_t)(rowBase + row) * Dmod + k0 + k8 * 8;
        size_t gB = (size_t)(colBase + row) * Dmod + k0 + k8 * 8;
        uint32_t so = sb + stage * 40960 + row * 80 + k8 * 16;
        cpa16(so + 0,     Ahi + gA);
        cpa16(so + 10240, Alo + gA);
        cpa16(so + 20480, Bhi + gB);
        cpa16(so + 30720, Blo + gB);
    }
    asm volatile("cp.async.commit_group;" ::: "memory");
}

__global__ __launch_bounds__(256) void gemm_kernel(
    const __nv_bfloat16* __restrict__ Ahi, const __nv_bfloat16* __restrict__ Alo,
    const float* __restrict__ bias, float* __restrict__ dOut, int mode)
{
    extern __shared__ __align__(128) char smx[];
    const uint32_t sb = smem_u32(smx);
    const int t = threadIdx.x;
    const int lane = t & 31, wid = t >> 5;
    const int warpM = wid & 3, warpN = wid >> 2;
    const int rowBase = blockIdx.x * 128;
    const int colBase = blockIdx.y * 128;
    const int z = (mode == 0) ? blockIdx.z : 3;
    const __nv_bfloat16* Bhi = g_whi + (size_t)z * Dmod * Dmod;
    const __nv_bfloat16* Blo = g_wlo + (size_t)z * Dmod * Dmod;

    float acc[2][8][4];
#pragma unroll
    for (int mi = 0; mi < 2; mi++)
#pragma unroll
        for (int nf = 0; nf < 8; nf++)
#pragma unroll
            for (int j = 0; j < 4; j++) acc[mi][nf][j] = 0.f;

    issue_chunk(Ahi, Alo, Bhi, Blo, sb, 0, 0, t, rowBase, colBase);

    for (int c = 0; c < 16; c++) {
        if (c < 15) {
            issue_chunk(Ahi, Alo, Bhi, Blo, sb, (c + 1) & 1, c + 1, t, rowBase, colBase);
            asm volatile("cp.async.wait_group 1;" ::: "memory");
        } else {
            asm volatile("cp.async.wait_group 0;" ::: "memory");
        }
        __syncthreads();

        const uint32_t sA = sb + (c & 1) * 40960;
#pragma unroll
        for (int pass = 0; pass < 3; pass++) {
            const uint32_t aOff = sA + ((pass == 2) ? 10240u : 0u);
            const uint32_t bOff = sA + ((pass == 1) ? 30720u : 20480u);
#pragma unroll
            for (int kk = 0; kk < 2; kk++) {
                uint32_t bfr[16];
#pragma unroll
                for (int g = 0; g < 4; g++) {
                    int row = warpN * 64 + g * 16 + (lane & 7) + (lane >> 4) * 8;
                    int col = kk * 16 + ((lane >> 3) & 1) * 8;
                    ldsm4(bfr[g * 4], bfr[g * 4 + 1], bfr[g * 4 + 2], bfr[g * 4 + 3],
                          bOff + row * 80 + col * 2);
                }
#pragma unroll
                for (int mi = 0; mi < 2; mi++) {
                    int row = warpM * 32 + mi * 16 + (lane & 15);
                    int col = kk * 16 + (lane >> 4) * 8;
                    uint32_t a0, a1, a2, a3;
                    ldsm4(a0, a1, a2, a3, aOff + row * 80 + col * 2);
#pragma unroll
                    for (int nf = 0; nf < 8; nf++) {
                        int g = nf >> 1, j = nf & 1;
                        mma16816(acc[mi][nf], a0, a1, a2, a3,
                                 bfr[g * 4 + j * 2], bfr[g * 4 + j * 2 + 1]);
                    }
                }
            }
        }
        __syncthreads();
    }

    // Epilogue. c-frag: rows m+{lane>>2, lane>>2+8}, cols nf*8 + (lane&3)*2 +{0,1}
    const int r0base = rowBase + warpM * 32 + (lane >> 2);
    if (mode == 0) {
        float* outp = (z == 0) ? g_q : (z == 1) ? g_k : g_v;
        const int h = (colBase + warpN * 64) >> 6;
#pragma unroll
        for (int mi = 0; mi < 2; mi++) {
            int r0 = r0base + mi * 16;
            int bb = r0 >> 12, n = r0 & 4095;
            float* rowp0 = outp + ((size_t)(bb * Hh + h) * Nseq + n) * DP;
            float* rowp1 = rowp0 + 8 * DP;
#pragma unroll
            for (int nf = 0; nf < 8; nf++) {
                int d = nf * 8 + (lane & 3) * 2;
                *(float2*)(rowp0 + d) = make_float2(acc[mi][nf][0], acc[mi][nf][1]);
                *(float2*)(rowp1 + d) = make_float2(acc[mi][nf][2], acc[mi][nf][3]);
            }
        }
    } else {
        const int col0 = colBase + warpN * 64;
#pragma unroll
        for (int mi = 0; mi < 2; mi++) {
            int r0 = r0base + mi * 16;
            float* p0 = dOut + (size_t)r0 * Dmod + col0;
            float* p1 = p0 + 8 * Dmod;
#pragma unroll
            for (int nf = 0; nf < 8; nf++) {
                int d = nf * 8 + (lane & 3) * 2;
                float2 bi = *(const float2*)(bias + col0 + d);
                *(float2*)(p0 + d) = make_float2(acc[mi][nf][0] + bi.x,
                                                 acc[mi][nf][1] + bi.y);
                *(float2*)(p1 + d) = make_float2(acc[mi][nf][2] + bi.x,
                                                 acc[mi][nf][3] + bi.y);
            }
        }
    }
}

// ---------------------------------------------------------------------------
// Kernel: low-rank projections (fp32, unchanged from R1)
// ---------------------------------------------------------------------------
__global__ __launch_bounds__(256) void proj_kernel(
    const float* __restrict__ E, const float* __restrict__ F)
{
    const int bh = blockIdx.x;
    const int h  = bh & 7;
    const float* A  = ((blockIdx.y == 0) ? E : F) + (size_t)h * Nseq * Rr;
    const float* Bm = ((blockIdx.y == 0) ? g_k : g_v) + (size_t)bh * Nseq * DP;
    float*       out = ((blockIdx.y == 0) ? g_kp : g_vp) + (size_t)bh * Rr * DP;

    __shared__ float Es[16 * 256];
    __shared__ float Ks[16 * 64];

    const int t = threadIdx.x;
    const int tr = t >> 3, td = t & 7;

    float acc[8][8];
#pragma unroll
    for (int i = 0; i < 8; i++)
#pragma unroll
        for (int j = 0; j < 8; j++) acc[i][j] = 0.f;

    for (int n0 = 0; n0 < Nseq; n0 += 16) {
#pragma unroll
        for (int u = 0; u < 4; u++) {
            int v = t + u * 256;
            int kn = v >> 6, rv = (v & 63) * 4;
            *(float4*)(Es + kn * 256 + rv) =
                *(const float4*)(A + (size_t)(n0 + kn) * Rr + rv);
        }
        {
            int kn = t >> 4, dv = (t & 15) * 4;
            *(float4*)(Ks + kn * 64 + dv) =
                *(const float4*)(Bm + (size_t)(n0 + kn) * DP + dv);
        }
        __syncthreads();
#pragma unroll
        for (int k = 0; k < 16; k++) {
            float a[8], b[8];
            float4 a0 = *(float4*)(Es + k * 256 + tr * 8);
            float4 a1 = *(float4*)(Es + k * 256 + tr * 8 + 4);
            a[0] = a0.x; a[1] = a0.y; a[2] = a0.z; a[3] = a0.w;
            a[4] = a1.x; a[5] = a1.y; a[6] = a1.z; a[7] = a1.w;
            float4 b0 = *(float4*)(Ks + k * 64 + td * 8);
            float4 b1 = *(float4*)(Ks + k * 64 + td * 8 + 4);
            b[0] = b0.x; b[1] = b0.y; b[2] = b0.z; b[3] = b0.w;
            b[4] = b1.x; b[5] = b1.y; b[6] = b1.z; b[7] = b1.w;
#pragma unroll
            for (int i = 0; i < 8; i++)
#pragma unroll
                for (int j = 0; j < 8; j++) acc[i][j] = fmaf(a[i], b[j], acc[i][j]);
        }
        __syncthreads();
    }

#pragma unroll
    for (int i = 0; i < 8; i++) {
        int r = tr * 8 + i;
        *(float4*)(out + (size_t)r * DP + td * 8) =
            make_float4(acc[i][0], acc[i][1], acc[i][2], acc[i][3]);
        *(float4*)(out + (size_t)r * DP + td * 8 + 4) =
            make_float4(acc[i][4], acc[i][5], acc[i][6], acc[i][7]);
    }
}

// ---------------------------------------------------------------------------
// Kernel: fused attention (fp32, unchanged from R1)
// ---------------------------------------------------------------------------
__global__ __launch_bounds__(256) void attn_kernel()
{
    extern __shared__ float sm[];
    float* kps  = sm;            // [64][256] d-major
    float* Qs   = sm + 16384;    // [64][64]
    float* vps  = sm + 20480;    // [256][64]
    float* attn = sm;            // [64][257] aliases kps/Qs

    const int t = threadIdx.x;
    const int bh = blockIdx.x, tile = blockIdx.y;
    const float* kp = g_kp + (size_t)bh * Rr * DP;
    const float* vp = g_vp + (size_t)bh * Rr * DP;
    const float* q  = g_q  + (size_t)bh * Nseq * DP + (size_t)tile * 64 * DP;

#pragma unroll
    for (int d0 = 0; d0 < 16; d0++) {
        float4 v = *(const float4*)(kp + (size_t)t * DP + d0 * 4);
        kps[(d0 * 4 + 0) * 256 + t] = v.x;
        kps[(d0 * 4 + 1) * 256 + t] = v.y;
        kps[(d0 * 4 + 2) * 256 + t] = v.z;
        kps[(d0 * 4 + 3) * 256 + t] = v.w;
    }
#pragma unroll
    for (int u = 0; u < 16; u++) {
        int v4 = t + u * 256;
        *(float4*)(vps + v4 * 4) = *(const float4*)(vp + v4 * 4);
    }
#pragma unroll
    for (int u = 0; u < 4; u++) {
        int v4 = t + u * 256;
        *(float4*)(Qs + v4 * 4) = *(const float4*)(q + v4 * 4);
    }
    __syncthreads();

    const int trow = t >> 5, lane = t & 31;
    float s[8][8];
#pragma unroll
    for (int i = 0; i < 8; i++)
#pragma unroll
        for (int j = 0; j < 8; j++) s[i][j] = 0.f;

#pragma unroll 16
    for (int kd = 0; kd < 64; kd++) {
        float a[8], b[8];
#pragma unroll
        for (int i = 0; i < 8; i++) a[i] = Qs[(trow * 8 + i) * 64 + kd];
        float4 b0 = *(float4*)(kps + kd * 256 + lane * 8);
        float4 b1 = *(float4*)(kps + kd * 256 + lane * 8 + 4);
        b[0] = b0.x; b[1] = b0.y; b[2] = b0.z; b[3] = b0.w;
        b[4] = b1.x; b[5] = b1.y; b[6] = b1.z; b[7] = b1.w;
#pragma unroll
        for (int i = 0; i < 8; i++)
#pragma unroll
            for (int j = 0; j < 8; j++) s[i][j] = fmaf(a[i], b[j], s[i][j]);
    }

#pragma unroll
    for (int i = 0; i < 8; i++) {
        float mx = s[i][0];
#pragma unroll
        for (int j = 1; j < 8; j++) mx = fmaxf(mx, s[i][j]);
        for (int o = 16; o > 0; o >>= 1)
            mx = fmaxf(mx, __shfl_xor_sync(0xffffffffu, mx, o));
        float sum = 0.f;
#pragma unroll
        for (int j = 0; j < 8; j++) {
            s[i][j] = __expf((s[i][j] - mx) * 0.125f);
            sum += s[i][j];
        }
        for (int o = 16; o > 0; o >>= 1)
            sum += __shfl_xor_sync(0xffffffffu, sum, o);
        float inv = 1.f / sum;
#pragma unroll
        for (int j = 0; j < 8; j++) s[i][j] *= inv;
    }

    __syncthreads();
#pragma unroll
    for (int i = 0; i < 8; i++)
#pragma unroll
        for (int j = 0; j < 8; j++)
            attn[(trow * 8 + i) * 257 + lane * 8 + j] = s[i][j];
    __syncthreads();

    const int trr = t >> 3, tq = t & 7;
    float o[2][8];
#pragma unroll
    for (int i = 0; i < 2; i++)
#pragma unroll
        for (int j = 0; j < 8; j++) o[i][j] = 0.f;

#pragma unroll 8
    for (int r = 0; r < Rr; r++) {
        float a0 = attn[(trr * 2 + 0) * 257 + r];
        float a1 = attn[(trr * 2 + 1) * 257 + r];
        float bb[8];
        float4 b0 = *(float4*)(vps + r * 64 + tq * 8);
        float4 b1 = *(float4*)(vps + r * 64 + tq * 8 + 4);
        bb[0] = b0.x; bb[1] = b0.y; bb[2] = b0.z; bb[3] = b0.w;
        bb[4] = b1.x; bb[5] = b1.y; bb[6] = b1.z; bb[7] = b1.w;
#pragma unroll
        for (int j = 0; j < 8; j++) {
            o[0][j] = fmaf(a0, bb[j], o[0][j]);
            o[1][j] = fmaf(a1, bb[j], o[1][j]);
        }
    }

    const int b = bh >> 3, h = bh & 7;
    const size_t base = ((size_t)(b * Nseq) + tile * 64) * Dmod + h * DP;
#pragma unroll
    for (int i = 0; i < 2; i++) {
        int row = trr * 2 + i;
        *(float4*)(g_cat + base + (size_t)row * Dmod + tq * 8) =
            make_float4(o[i][0], o[i][1], o[i][2], o[i][3]);
        *(float4*)(g_cat + base + (size_t)row * Dmod + tq * 8 + 4) =
            make_float4(o[i][4], o[i][5], o[i][6], o[i][7]);
    }
}

// ---------------------------------------------------------------------------
extern "C" void kernel_launch(void* const* d_in, const int* in_sizes, int n_in,
                              void* d_out, int out_size)
{
    const float* x  = (const float*)d_in[0];
    const float* wq = (const float*)d_in[1];
    const float* wk = (const float*)d_in[2];
    const float* wv = (const float*)d_in[3];
    const float* E  = (const float*)d_in[4];
    const float* F  = (const float*)d_in[5];
    const float* wd = (const float*)d_in[6];
    const float* bd = (const float*)d_in[7];
    float* out = (float*)d_out;

    __nv_bfloat16 *xhi, *xlo, *chi, *clo;
    cudaGetSymbolAddress((void**)&xhi, g_xhi);
    cudaGetSymbolAddress((void**)&xlo, g_xlo);
    cudaGetSymbolAddress((void**)&chi, g_chi);
    cudaGetSymbolAddress((void**)&clo, g_clo);
    float* catp;
    cudaGetSymbolAddress((void**)&catp, g_cat);

    cudaFuncSetAttribute(gemm_kernel,
                         cudaFuncAttributeMaxDynamicSharedMemorySize, 81920);
    cudaFuncSetAttribute(attn_kernel,
                         cudaFuncAttributeMaxDynamicSharedMemorySize, 147456);

    // split inputs + weights
    split_kernel<<<(MT * Dmod) / 1024, 256>>>(x, xhi, xlo);
    convw_kernel<<<dim3(16, 16, 4), dim3(32, 8)>>>(wq, wk, wv, wd);

    // QKV via mma.sync split-bf16
    gemm_kernel<<<dim3(MT / 128, 4, 3), 256, 81920>>>(xhi, xlo, nullptr, nullptr, 0);

    proj_kernel<<<dim3(BH, 2), 256>>>(E, F);
    attn_kernel<<<dim3(BH, Nseq / 64), 256, 147456>>>();

    // dense via mma.sync split-bf16
    split_kernel<<<(MT * Dmod) / 1024, 256>>>(catp, chi, clo);
    gemm_kernel<<<dim3(MT / 128, 4, 1), 256, 81920>>>(chi, clo, bd, out, 1);
}

// round 4
// speedup vs baseline: 2.8185x; 1.8015x over previous
#include <cuda_runtime.h>
#include <cuda_bf16.h>
#include <stdint.h>
#include <math.h>

// Problem constants
#define Bdim 8
#define Nseq 4096
#define Dmod 512
#define Hh   8
#define Rr   256
#define DP   64
#define BH   64          // Bdim*Hh
#define MT   32768       // Bdim*Nseq

// ---------------------------------------------------------------------------
// Scratch (module-static device memory)
// ---------------------------------------------------------------------------
__device__ __nv_bfloat16 g_xhi[(size_t)MT * Dmod];
__device__ __nv_bfloat16 g_xlo[(size_t)MT * Dmod];
__device__ __nv_bfloat16 g_whi[4 * Dmod * Dmod];   // [z][n][k] transposed
__device__ __nv_bfloat16 g_wlo[4 * Dmod * Dmod];
__device__ __nv_bfloat16 g_ehi[(size_t)Hh * Nseq * Rr];
__device__ __nv_bfloat16 g_elo[(size_t)Hh * Nseq * Rr];
__device__ __nv_bfloat16 g_fhi[(size_t)Hh * Nseq * Rr];
__device__ __nv_bfloat16 g_flo[(size_t)Hh * Nseq * Rr];
__device__ __nv_bfloat16 g_qhi[(size_t)BH * Nseq * DP];
__device__ __nv_bfloat16 g_qlo[(size_t)BH * Nseq * DP];
__device__ __nv_bfloat16 g_khi[(size_t)BH * Nseq * DP];
__device__ __nv_bfloat16 g_klo[(size_t)BH * Nseq * DP];
__device__ __nv_bfloat16 g_vhi[(size_t)BH * Nseq * DP];
__device__ __nv_bfloat16 g_vlo[(size_t)BH * Nseq * DP];
__device__ float         g_part[(size_t)8 * 1048576];   // [ef][ksplit][bh][256][64]
__device__ __nv_bfloat16 g_kphi[(size_t)BH * Rr * DP];
__device__ __nv_bfloat16 g_kplo[(size_t)BH * Rr * DP];
__device__ __nv_bfloat16 g_vphi[(size_t)BH * Rr * DP];
__device__ __nv_bfloat16 g_vplo[(size_t)BH * Rr * DP];
__device__ __nv_bfloat16 g_chi[(size_t)MT * Dmod];
__device__ __nv_bfloat16 g_clo[(size_t)MT * Dmod];

// ---------------------------------------------------------------------------
// PTX helpers (compute_103-safe)
// ---------------------------------------------------------------------------
__device__ __forceinline__ uint32_t smem_u32(const void* p) {
    uint32_t a;
    asm("{ .reg .u64 t; cvta.to.shared.u64 t, %1; cvt.u32.u64 %0, t; }" : "=r"(a) : "l"(p));
    return a;
}
__device__ __forceinline__ void cpa16(uint32_t dst, const void* src) {
    asm volatile("cp.async.cg.shared.global [%0], [%1], 16;" :: "r"(dst), "l"(src));
}
__device__ __forceinline__ void ldsm4(uint32_t& r0, uint32_t& r1, uint32_t& r2,
                                      uint32_t& r3, uint32_t addr) {
    asm volatile("ldmatrix.sync.aligned.m8n8.x4.shared.b16 {%0,%1,%2,%3}, [%4];"
                 : "=r"(r0), "=r"(r1), "=r"(r2), "=r"(r3) : "r"(addr));
}
__device__ __forceinline__ void ldsm4t(uint32_t& r0, uint32_t& r1, uint32_t& r2,
                                       uint32_t& r3, uint32_t addr) {
    asm volatile("ldmatrix.sync.aligned.m8n8.x4.trans.shared.b16 {%0,%1,%2,%3}, [%4];"
                 : "=r"(r0), "=r"(r1), "=r"(r2), "=r"(r3) : "r"(addr));
}
__device__ __forceinline__ void mma16816(float* c, uint32_t a0, uint32_t a1,
                                         uint32_t a2, uint32_t a3,
                                         uint32_t b0, uint32_t b1) {
    asm volatile(
        "mma.sync.aligned.m16n8k16.row.col.f32.bf16.bf16.f32 "
        "{%0,%1,%2,%3}, {%4,%5,%6,%7}, {%8,%9}, {%0,%1,%2,%3};"
        : "+f"(c[0]), "+f"(c[1]), "+f"(c[2]), "+f"(c[3])
        : "r"(a0), "r"(a1), "r"(a2), "r"(a3), "r"(b0), "r"(b1));
}
// split two floats into packed bf16x2 hi + lo
__device__ __forceinline__ uint32_t fsplit2(float a, float b, uint32_t& lo) {
    __nv_bfloat16 ha = __float2bfloat16(a), hb = __float2bfloat16(b);
    __nv_bfloat16 la = __float2bfloat16(a - __bfloat162float(ha));
    __nv_bfloat16 lb = __float2bfloat16(b - __bfloat162float(hb));
    __nv_bfloat162 H = __halves2bfloat162(ha, hb);
    __nv_bfloat162 L = __halves2bfloat162(la, lb);
    lo = *(uint32_t*)&L;
    return *(uint32_t*)&H;
}
// fast exp2 via degree-6 Taylor (rel err ~1.6e-5) — FMA pipe, no MUFU
__device__ __forceinline__ float fexp2(float x) {
    x = fmaxf(x, -120.f);
    float xi = floorf(x);
    float f = x - xi;
    float p = 1.54035304e-4f;
    p = fmaf(p, f, 1.33335581e-3f);
    p = fmaf(p, f, 9.61812911e-3f);
    p = fmaf(p, f, 5.55041087e-2f);
    p = fmaf(p, f, 2.40226507e-1f);
    p = fmaf(p, f, 6.93147181e-1f);
    p = fmaf(p, f, 1.0f);
    return p * __int_as_float(((int)xi + 127) << 23);
}

// ---------------------------------------------------------------------------
// split: fp32 -> (hi, lo) bf16  (element count must be multiple of 1024)
// ---------------------------------------------------------------------------
__global__ __launch_bounds__(256) void split_kernel(
    const float* __restrict__ in, __nv_bfloat16* __restrict__ hi,
    __nv_bfloat16* __restrict__ lo)
{
    size_t i = ((size_t)blockIdx.x * 256 + threadIdx.x) * 4;
    float4 v = *(const float4*)(in + i);
    uint32_t l0, l1;
    uint32_t h0 = fsplit2(v.x, v.y, l0);
    uint32_t h1 = fsplit2(v.z, v.w, l1);
    *(uint32_t*)(hi + i)     = h0;
    *(uint32_t*)(hi + i + 2) = h1;
    *(uint32_t*)(lo + i)     = l0;
    *(uint32_t*)(lo + i + 2) = l1;
}

// transpose + split weights: g_w{hi,lo}[z][n][k] = split(w_z[k][n])
__global__ __launch_bounds__(256) void convw_kernel(
    const float* __restrict__ wq, const float* __restrict__ wk,
    const float* __restrict__ wv, const float* __restrict__ wd)
{
    const int z = blockIdx.z;
    const float* w = (z == 0) ? wq : (z == 1) ? wk : (z == 2) ? wv : wd;
    __shared__ float tile[32][33];
    const int k0 = blockIdx.x * 32, n0 = blockIdx.y * 32;
    const int tx = threadIdx.x, ty = threadIdx.y;   // block (32, 8)
#pragma unroll
    for (int i = 0; i < 4; i++)
        tile[ty + i * 8][tx] = w[(size_t)(k0 + ty + i * 8) * Dmod + n0 + tx];
    __syncthreads();
#pragma unroll
    for (int i = 0; i < 4; i++) {
        float x = tile[tx][ty + i * 8];
        __nv_bfloat16 h = __float2bfloat16(x);
        size_t o = (size_t)z * Dmod * Dmod + (size_t)(n0 + ty + i * 8) * Dmod + k0 + tx;
        g_whi[o] = h;
        g_wlo[o] = __float2bfloat16(x - __bfloat162float(h));
    }
}

// ---------------------------------------------------------------------------
// mma.sync split-bf16 GEMM: C(128x128) = A(Mx512) @ W(512x512)
// mode 0: qkv (z = blockIdx.z) -> writes q/k/v as bf16 hi/lo in bhnd layout
// mode 1: dense (z = 3) -> fp32 + bias -> dOut
// ---------------------------------------------------------------------------
__device__ __forceinline__ void issue_chunk(
    const __nv_bfloat16* __restrict__ Ahi, const __nv_bfloat16* __restrict__ Alo,
    const __nv_bfloat16* __restrict__ Bhi, const __nv_bfloat16* __restrict__ Blo,
    uint32_t sb, int stage, int c, int t, int rowBase, int colBase)
{
    const int k0 = c * 32;
#pragma unroll
    for (int u = 0; u < 2; u++) {
        int id = t + u * 256;
        int row = id >> 2, k8 = id & 3;
        size_t gA = (size_t)(rowBase + row) * Dmod + k0 + k8 * 8;
        size_t gB = (size_t)(colBase + row) * Dmod + k0 + k8 * 8;
        uint32_t so = sb + stage * 40960 + row * 80 + k8 * 16;
        cpa16(so + 0,     Ahi + gA);
        cpa16(so + 10240, Alo + gA);
        cpa16(so + 20480, Bhi + gB);
        cpa16(so + 30720, Blo + gB);
    }
    asm volatile("cp.async.commit_group;" ::: "memory");
}

__global__ __launch_bounds__(256) void gemm_kernel(
    const __nv_bfloat16* __restrict__ Ahi, const __nv_bfloat16* __restrict__ Alo,
    const float* __restrict__ bias, float* __restrict__ dOut, int mode)
{
    extern __shared__ __align__(128) char smx[];
    const uint32_t sb = smem_u32(smx);
    const int t = threadIdx.x;
    const int lane = t & 31, wid = t >> 5;
    const int warpM = wid & 3, warpN = wid >> 2;
    const int rowBase = blockIdx.x * 128;
    const int colBase = blockIdx.y * 128;
    const int z = (mode == 0) ? blockIdx.z : 3;
    const __nv_bfloat16* Bhi = g_whi + (size_t)z * Dmod * Dmod;
    const __nv_bfloat16* Blo = g_wlo + (size_t)z * Dmod * Dmod;

    float acc[2][8][4];
#pragma unroll
    for (int mi = 0; mi < 2; mi++)
#pragma unroll
        for (int nf = 0; nf < 8; nf++)
#pragma unroll
            for (int j = 0; j < 4; j++) acc[mi][nf][j] = 0.f;

    issue_chunk(Ahi, Alo, Bhi, Blo, sb, 0, 0, t, rowBase, colBase);

    for (int c = 0; c < 16; c++) {
        if (c < 15) {
            issue_chunk(Ahi, Alo, Bhi, Blo, sb, (c + 1) & 1, c + 1, t, rowBase, colBase);
            asm volatile("cp.async.wait_group 1;" ::: "memory");
        } else {
            asm volatile("cp.async.wait_group 0;" ::: "memory");
        }
        __syncthreads();

        const uint32_t sA = sb + (c & 1) * 40960;
#pragma unroll
        for (int pass = 0; pass < 3; pass++) {
            const uint32_t aOff = sA + ((pass == 2) ? 10240u : 0u);
            const uint32_t bOff = sA + ((pass == 1) ? 30720u : 20480u);
#pragma unroll
            for (int kk = 0; kk < 2; kk++) {
                uint32_t bfr[16];
#pragma unroll
                for (int g = 0; g < 4; g++) {
                    int row = warpN * 64 + g * 16 + (lane & 7) + (lane >> 4) * 8;
                    int col = kk * 16 + ((lane >> 3) & 1) * 8;
                    ldsm4(bfr[g * 4], bfr[g * 4 + 1], bfr[g * 4 + 2], bfr[g * 4 + 3],
                          bOff + row * 80 + col * 2);
                }
#pragma unroll
                for (int mi = 0; mi < 2; mi++) {
                    int row = warpM * 32 + mi * 16 + (lane & 15);
                    int col = kk * 16 + (lane >> 4) * 8;
                    uint32_t a0, a1, a2, a3;
                    ldsm4(a0, a1, a2, a3, aOff + row * 80 + col * 2);
#pragma unroll
                    for (int nf = 0; nf < 8; nf++) {
                        int g = nf >> 1, j = nf & 1;
                        mma16816(acc[mi][nf], a0, a1, a2, a3,
                                 bfr[g * 4 + j * 2], bfr[g * 4 + j * 2 + 1]);
                    }
                }
            }
        }
        __syncthreads();
    }

    const int r0base = rowBase + warpM * 32 + (lane >> 2);
    if (mode == 0) {
        __nv_bfloat16* oh = (z == 0) ? g_qhi : (z == 1) ? g_khi : g_vhi;
        __nv_bfloat16* ol = (z == 0) ? g_qlo : (z == 1) ? g_klo : g_vlo;
        const int h = (colBase + warpN * 64) >> 6;
#pragma unroll
        for (int mi = 0; mi < 2; mi++) {
            int r0 = r0base + mi * 16;
            int bb = r0 >> 12, n = r0 & 4095;
            size_t rb0 = ((size_t)(bb * Hh + h) * Nseq + n) * DP;
            size_t rb1 = rb0 + 8 * DP;
#pragma unroll
            for (int nf = 0; nf < 8; nf++) {
                int d = nf * 8 + (lane & 3) * 2;
                uint32_t lo0, lo1;
                uint32_t hi0 = fsplit2(acc[mi][nf][0], acc[mi][nf][1], lo0);
                uint32_t hi1 = fsplit2(acc[mi][nf][2], acc[mi][nf][3], lo1);
                *(uint32_t*)(oh + rb0 + d) = hi0;
                *(uint32_t*)(ol + rb0 + d) = lo0;
                *(uint32_t*)(oh + rb1 + d) = hi1;
                *(uint32_t*)(ol + rb1 + d) = lo1;
            }
        }
    } else {
        const int col0 = colBase + warpN * 64;
#pragma unroll
        for (int mi = 0; mi < 2; mi++) {
            int r0 = r0base + mi * 16;
            float* p0 = dOut + (size_t)r0 * Dmod + col0;
            float* p1 = p0 + 8 * Dmod;
#pragma unroll
            for (int nf = 0; nf < 8; nf++) {
                int d = nf * 8 + (lane & 3) * 2;
                float2 bi = *(const float2*)(bias + col0 + d);
                *(float2*)(p0 + d) = make_float2(acc[mi][nf][0] + bi.x,
                                                 acc[mi][nf][1] + bi.y);
                *(float2*)(p1 + d) = make_float2(acc[mi][nf][2] + bi.x,
                                                 acc[mi][nf][3] + bi.y);
            }
        }
    }
}

// ---------------------------------------------------------------------------
// proj: kp/vp[r,d] = sum_n E/F[h,n,r] * k/v[bh,n,d] via mma (trans ldmatrix).
// grid (128, 4): x = ef*64+bh, y = ksplit (K=1024 each). Writes fp32 partials.
// smem stage: Ehi[32n][264r] 16896B, Elo 16896, Khi[32n][72d] 4608, Klo 4608;
// stage stride 43008, double buffered = 86016 B.
// ---------------------------------------------------------------------------
#define PEHI 0
#define PELO 16896
#define PKHI 33792
#define PKLO 38400
#define PSTG 43008

__global__ __launch_bounds__(256) void proj_kernel()
{
    extern __shared__ __align__(128) char smx[];
    const uint32_t sb = smem_u32(smx);
    const int t = threadIdx.x, lane = t & 31, wid = t >> 5;
    const int warpM = wid & 3, warpN = wid >> 2;   // r, d
    const int bh = blockIdx.x & 63, ef = blockIdx.x >> 6;
    const int ks = blockIdx.y;
    const int h = bh & 7;

    const __nv_bfloat16* Eh = (ef ? g_fhi : g_ehi) + (size_t)h * Nseq * Rr;
    const __nv_bfloat16* El = (ef ? g_flo : g_elo) + (size_t)h * Nseq * Rr;
    const __nv_bfloat16* Kh = (ef ? g_vhi : g_khi) + (size_t)bh * Nseq * DP;
    const __nv_bfloat16* Kl = (ef ? g_vlo : g_klo) + (size_t)bh * Nseq * DP;
    float* part = g_part + (((size_t)ef * 4 + ks) * 64 + bh) * 16384;

    const int nBase = ks * 1024;
    const int r0 = warpM * 64, d0 = warpN * 32;

    float acc[16][4];
#pragma unroll
    for (int i = 0; i < 16; i++)
#pragma unroll
        for (int j = 0; j < 4; j++) acc[i][j] = 0.f;

    auto issue = [&](int stage, int c) {
        const int n0 = nBase + c * 32;
        const uint32_t so = sb + stage * PSTG;
#pragma unroll
        for (int u = 0; u < 4; u++) {
            int id = u * 256 + t;
            int row = id >> 5, seg = id & 31;
            cpa16(so + PEHI + row * 528 + seg * 16, Eh + (size_t)(n0 + row) * Rr + seg * 8);
            cpa16(so + PELO + row * 528 + seg * 16, El + (size_t)(n0 + row) * Rr + seg * 8);
        }
        {
            int row = t >> 3, seg = t & 7;
            cpa16(so + PKHI + row * 144 + seg * 16, Kh + (size_t)(n0 + row) * DP + seg * 8);
            cpa16(so + PKLO + row * 144 + seg * 16, Kl + (size_t)(n0 + row) * DP + seg * 8);
        }
        asm volatile("cp.async.commit_group;" ::: "memory");
    };

    issue(0, 0);
    for (int c = 0; c < 32; c++) {
        if (c < 31) {
            issue((c + 1) & 1, c + 1);
            asm volatile("cp.async.wait_group 1;" ::: "memory");
        } else {
            asm volatile("cp.async.wait_group 0;" ::: "memory");
        }
        __syncthreads();

        const uint32_t st = sb + (c & 1) * PSTG;
#pragma unroll
        for (int kk = 0; kk < 2; kk++) {
            // A = E^T via trans: lane -> krow = kk*16+(l&7)+bit4*8, mcol = +bit3*8
            uint32_t ah[4][4], al[4][4];
            const int krA = kk * 16 + (lane & 7) + ((lane >> 4) & 1) * 8;
#pragma unroll
            for (int mf = 0; mf < 4; mf++) {
                uint32_t off = krA * 528 + (r0 + mf * 16 + ((lane >> 3) & 1) * 8) * 2;
                ldsm4t(ah[mf][0], ah[mf][1], ah[mf][2], ah[mf][3], st + PEHI + off);
                ldsm4t(al[mf][0], al[mf][1], al[mf][2], al[mf][3], st + PELO + off);
            }
            // B = K via trans: krow = kk*16+(l&7)+bit3*8, ncol = +bit4*8
            const int krB = kk * 16 + (lane & 7) + ((lane >> 3) & 1) * 8;
#pragma unroll
            for (int g2 = 0; g2 < 2; g2++) {
                uint32_t off = krB * 144 + (d0 + g2 * 16 + ((lane >> 4) & 1) * 8) * 2;
                uint32_t b0, b1, b2, b3, l0, l1, l2, l3;
                ldsm4t(b0, b1, b2, b3, st + PKHI + off);
                ldsm4t(l0, l1, l2, l3, st + PKLO + off);
#pragma unroll
                for (int mf = 0; mf < 4; mf++) {
                    float* c0 = acc[mf * 4 + g2 * 2];
                    float* c1 = acc[mf * 4 + g2 * 2 + 1];
                    mma16816(c0, ah[mf][0], ah[mf][1], ah[mf][2], ah[mf][3], b0, b1);
                    mma16816(c1, ah[mf][0], ah[mf][1], ah[mf][2], ah[mf][3], b2, b3);
                    mma16816(c0, ah[mf][0], ah[mf][1], ah[mf][2], ah[mf][3], l0, l1);
                    mma16816(c1, ah[mf][0], ah[mf][1], ah[mf][2], ah[mf][3], l2, l3);
                    mma16816(c0, al[mf][0], al[mf][1], al[mf][2], al[mf][3], b0, b1);
                    mma16816(c1, al[mf][0], al[mf][1], al[mf][2], al[mf][3], b2, b3);
                }
            }
        }
        __syncthreads();
    }

#pragma unroll
    for (int mf = 0; mf < 4; mf++) {
        int r = r0 + mf * 16 + (lane >> 2);
#pragma unroll
        for (int f = 0; f < 4; f++) {
            int d = d0 + f * 8 + (lane & 3) * 2;
            *(float2*)(part + r * 64 + d) =
                make_float2(acc[mf * 4 + f][0], acc[mf * 4 + f][1]);
            *(float2*)(part + (r + 8) * 64 + d) =
                make_float2(acc[mf * 4 + f][2], acc[mf * 4 + f][3]);
        }
    }
}

// reduce 4 K-split partials -> split to bf16 hi/lo kp/vp. grid (1024, 2).
__global__ __launch_bounds__(256) void reduce_kernel()
{
    const int ef = blockIdx.y;
    size_t base = ((size_t)blockIdx.x * 256 + threadIdx.x) * 4;
    const float* p = g_part + (size_t)ef * 4194304 + base;
    float4 s0 = *(const float4*)(p);
    float4 s1 = *(const float4*)(p + 1048576);
    float4 s2 = *(const float4*)(p + 2097152);
    float4 s3 = *(const float4*)(p + 3145728);
    float a = s0.x + s1.x + s2.x + s3.x;
    float b = s0.y + s1.y + s2.y + s3.y;
    float c = s0.z + s1.z + s2.z + s3.z;
    float d = s0.w + s1.w + s2.w + s3.w;
    __nv_bfloat16* hi = ef ? g_vphi : g_kphi;
    __nv_bfloat16* lo = ef ? g_vplo : g_kplo;
    uint32_t l0, l1;
    uint32_t h0 = fsplit2(a, b, l0);
    uint32_t h1 = fsplit2(c, d, l1);
    *(uint32_t*)(hi + base)     = h0;
    *(uint32_t*)(hi + base + 2) = h1;
    *(uint32_t*)(lo + base)     = l0;
    *(uint32_t*)(lo + base + 2) = l1;
}

// ---------------------------------------------------------------------------
// attn: per block one (b,h) + 128 q rows. All-mma, register softmax, poly exp2.
// smem: Qhi 0 / Qlo 18432 (128x72), kphi 36864 / kplo 73728 (256x72),
//       vphi 110592 / vplo 147456 (256x72). Total 184320 B.
// ---------------------------------------------------------------------------
#define AQHI 0
#define AQLO 18432
#define AKPHI 36864
#define AKPLO 73728
#define AVPHI 110592
#define AVPLO 147456

__global__ __launch_bounds__(256) void attn_kernel()
{
    extern __shared__ __align__(128) char smx[];
    const uint32_t sb = smem_u32(smx);
    const int t = threadIdx.x, lane = t & 31, w = t >> 5;
    const int bh = blockIdx.x, tile = blockIdx.y;

    const __nv_bfloat16* qh = g_qhi + ((size_t)bh * Nseq + tile * 128) * DP;
    const __nv_bfloat16* ql = g_qlo + ((size_t)bh * Nseq + tile * 128) * DP;
    const __nv_bfloat16* kh = g_kphi + (size_t)bh * Rr * DP;
    const __nv_bfloat16* kl = g_kplo + (size_t)bh * Rr * DP;
    const __nv_bfloat16* vh = g_vphi + (size_t)bh * Rr * DP;
    const __nv_bfloat16* vl = g_vplo + (size_t)bh * Rr * DP;

#pragma unroll
    for (int u = 0; u < 4; u++) {
        int id = u * 256 + t, row = id >> 3, seg = id & 7;
        cpa16(sb + AQHI + row * 144 + seg * 16, qh + row * 64 + seg * 8);
        cpa16(sb + AQLO + row * 144 + seg * 16, ql + row * 64 + seg * 8);
    }
#pragma unroll
    for (int u = 0; u < 8; u++) {
        int id = u * 256 + t, row = id >> 3, seg = id & 7;
        cpa16(sb + AKPHI + row * 144 + seg * 16, kh + row * 64 + seg * 8);
        cpa16(sb + AKPLO + row * 144 + seg * 16, kl + row * 64 + seg * 8);
        cpa16(sb + AVPHI + row * 144 + seg * 16, vh + row * 64 + seg * 8);
        cpa16(sb + AVPLO + row * 144 + seg * 16, vl + row * 64 + seg * 8);
    }
    asm volatile("cp.async.commit_group;" ::: "memory");
    asm volatile("cp.async.wait_group 0;" ::: "memory");
    __syncthreads();

    // GEMM1: scores[16 rows][256] per warp; frags c[2nb+nf]
    const int m0 = w * 16;
    float c[32][4];
#pragma unroll
    for (int i = 0; i < 32; i++)
#pragma unroll
        for (int j = 0; j < 4; j++) c[i][j] = 0.f;

#pragma unroll
    for (int kk = 0; kk < 4; kk++) {
        uint32_t ah0, ah1, ah2, ah3, al0, al1, al2, al3;
        {
            uint32_t ar = (m0 + (lane & 15)) * 144 + (kk * 16 + (lane >> 4) * 8) * 2;
            ldsm4(ah0, ah1, ah2, ah3, sb + AQHI + ar);
            ldsm4(al0, al1, al2, al3, sb + AQLO + ar);
        }
#pragma unroll
        for (int nb = 0; nb < 16; nb++) {
            uint32_t br = (nb * 16 + (lane & 7) + ((lane >> 4) & 1) * 8) * 144
                        + (kk * 16 + ((lane >> 3) & 1) * 8) * 2;
            uint32_t b0, b1, b2, b3, l0, l1, l2, l3;
            ldsm4(b0, b1, b2, b3, sb + AKPHI + br);
            ldsm4(l0, l1, l2, l3, sb + AKPLO + br);
            mma16816(c[2 * nb],     ah0, ah1, ah2, ah3, b0, b1);
            mma16816(c[2 * nb + 1], ah0, ah1, ah2, ah3, b2, b3);
            mma16816(c[2 * nb],     ah0, ah1, ah2, ah3, l0, l1);
            mma16816(c[2 * nb + 1], ah0, ah1, ah2, ah3, l2, l3);
            mma16816(c[2 * nb],     al0, al1, al2, al3, b0, b1);
            mma16816(c[2 * nb + 1], al0, al1, al2, al3, b2, b3);
        }
    }

    // softmax: rows r0 = lane>>2 and r0+8; exp(x*0.125) = exp2(x*C)
    const float C = 0.125f * 1.4426950408889634f;
    float mx0 = -1e30f, mx1 = -1e30f;
#pragma unroll
    for (int f = 0; f < 32; f++) {
        mx0 = fmaxf(mx0, fmaxf(c[f][0], c[f][1]));
        mx1 = fmaxf(mx1, fmaxf(c[f][2], c[f][3]));
    }
    mx0 = fmaxf(mx0, __shfl_xor_sync(0xffffffffu, mx0, 1));
    mx0 = fmaxf(mx0, __shfl_xor_sync(0xffffffffu, mx0, 2));
    mx1 = fmaxf(mx1, __shfl_xor_sync(0xffffffffu, mx1, 1));
    mx1 = fmaxf(mx1, __shfl_xor_sync(0xffffffffu, mx1, 2));
    float s0 = 0.f, s1 = 0.f;
#pragma unroll
    for (int f = 0; f < 32; f++) {
        c[f][0] = fexp2((c[f][0] - mx0) * C);
        c[f][1] = fexp2((c[f][1] - mx0) * C);
        c[f][2] = fexp2((c[f][2] - mx1) * C);
        c[f][3] = fexp2((c[f][3] - mx1) * C);
        s0 += c[f][0] + c[f][1];
        s1 += c[f][2] + c[f][3];
    }
    s0 += __shfl_xor_sync(0xffffffffu, s0, 1);
    s0 += __shfl_xor_sync(0xffffffffu, s0, 2);
    s1 += __shfl_xor_sync(0xffffffffu, s1, 1);
    s1 += __shfl_xor_sync(0xffffffffu, s1, 2);
    const float inv0 = 1.f / s0, inv1 = 1.f / s1;

    // pack P into A-fragments (hi/lo): frag f -> phi[(f>>1)*4 + (f&1)*2 + {0,1}]
    uint32_t phi[64], plo[64];
#pragma unroll
    for (int f = 0; f < 32; f++) {
        float p0 = c[f][0] * inv0, p1 = c[f][1] * inv0;
        float p2 = c[f][2] * inv1, p3 = c[f][3] * inv1;
        int base = (f >> 1) * 4 + (f & 1) * 2;
        uint32_t lo0, lo1;
        phi[base]     = fsplit2(p0, p1, lo0);
        phi[base + 1] = fsplit2(p2, p3, lo1);
        plo[base]     = lo0;
        plo[base + 1] = lo1;
    }

    // GEMM2: out[16][64] = P @ vp; vp via trans ldmatrix
    float o[8][4];
#pragma unroll
    for (int i = 0; i < 8; i++)
#pragma unroll
        for (int j = 0; j < 4; j++) o[i][j] = 0.f;

#pragma unroll
    for (int ks = 0; ks < 16; ks++) {
        uint32_t A0 = phi[ks * 4], A1 = phi[ks * 4 + 1];
        uint32_t A2 = phi[ks * 4 + 2], A3 = phi[ks * 4 + 3];
        uint32_t L0 = plo[ks * 4], L1 = plo[ks * 4 + 1];
        uint32_t L2 = plo[ks * 4 + 2], L3 = plo[ks * 4 + 3];
        const int krB = ks * 16 + (lane & 7) + ((lane >> 3) & 1) * 8;
#pragma unroll
        for (int g2 = 0; g2 < 4; g2++) {
            uint32_t off = krB * 144 + (g2 * 16 + ((lane >> 4) & 1) * 8) * 2;
            uint32_t b0, b1, b2, b3, l0, l1, l2, l3;
            ldsm4t(b0, b1, b2, b3, sb + AVPHI + off);
            ldsm4t(l0, l1, l2, l3, sb + AVPLO + off);
            mma16816(o[g2 * 2],     A0, A1, A2, A3, b0, b1);
            mma16816(o[g2 * 2 + 1], A0, A1, A2, A3, b2, b3);
            mma16816(o[g2 * 2],     A0, A1, A2, A3, l0, l1);
            mma16816(o[g2 * 2 + 1], A0, A1, A2, A3, l2, l3);
            mma16816(o[g2 * 2],     L0, L1, L2, L3, b0, b1);
            mma16816(o[g2 * 2 + 1], L0, L1, L2, L3, b2, b3);
        }
    }

    // epilogue: split to bf16 hi/lo, write concat layout
    const int n0 = tile * 128 + m0 + (lane >> 2);
    const int b = bh >> 3, h = bh & 7;
#pragma unroll
    for (int f = 0; f < 8; f++) {
        int d = f * 8 + (lane & 3) * 2;
        size_t i0 = (size_t)(b * Nseq + n0) * Dmod + h * 64 + d;
        size_t i1 = i0 + (size_t)8 * Dmod;
        uint32_t lo0, lo1;
        uint32_t hi0 = fsplit2(o[f][0], o[f][1], lo0);
        uint32_t hi1 = fsplit2(o[f][2], o[f][3], lo1);
        *(uint32_t*)(g_chi + i0) = hi0;
        *(uint32_t*)(g_clo + i0) = lo0;
        *(uint32_t*)(g_chi + i1) = hi1;
        *(uint32_t*)(g_clo + i1) = lo1;
    }
}

// ---------------------------------------------------------------------------
extern "C" void kernel_launch(void* const* d_in, const int* in_sizes, int n_in,
                              void* d_out, int out_size)
{
    const float* x  = (const float*)d_in[0];
    const float* wq = (const float*)d_in[1];
    const float* wk = (const float*)d_in[2];
    const float* wv = (const float*)d_in[3];
    const float* E  = (const float*)d_in[4];
    const float* F  = (const float*)d_in[5];
    const float* wd = (const float*)d_in[6];
    const float* bd = (const float*)d_in[7];
    float* out = (float*)d_out;

    __nv_bfloat16 *xhi, *xlo, *ehi, *elo, *fhi, *flo, *chi, *clo;
    cudaGetSymbolAddress((void**)&xhi, g_xhi);
    cudaGetSymbolAddress((void**)&xlo, g_xlo);
    cudaGetSymbolAddress((void**)&ehi, g_ehi);
    cudaGetSymbolAddress((void**)&elo, g_elo);
    cudaGetSymbolAddress((void**)&fhi, g_fhi);
    cudaGetSymbolAddress((void**)&flo, g_flo);
    cudaGetSymbolAddress((void**)&chi, g_chi);
    cudaGetSymbolAddress((void**)&clo, g_clo);

    cudaFuncSetAttribute(gemm_kernel,
                         cudaFuncAttributeMaxDynamicSharedMemorySize, 81920);
    cudaFuncSetAttribute(proj_kernel,
                         cudaFuncAttributeMaxDynamicSharedMemorySize, 86016);
    cudaFuncSetAttribute(attn_kernel,
                         cudaFuncAttributeMaxDynamicSharedMemorySize, 184320);

    // splits
    split_kernel<<<(MT * Dmod) / 1024, 256>>>(x, xhi, xlo);
    split_kernel<<<(Hh * Nseq * Rr) / 1024, 256>>>(E, ehi, elo);
    split_kernel<<<(Hh * Nseq * Rr) / 1024, 256>>>(F, fhi, flo);
    convw_kernel<<<dim3(16, 16, 4), dim3(32, 8)>>>(wq, wk, wv, wd);

    // QKV -> bf16 hi/lo q,k,v
    gemm_kernel<<<dim3(MT / 128, 4, 3), 256, 81920>>>(xhi, xlo, nullptr, nullptr, 0);

    // low-rank projections -> partials -> kp/vp hi/lo
    proj_kernel<<<dim3(128, 4), 256, 86016>>>();
    reduce_kernel<<<dim3(1024, 2), 256>>>();

    // fused attention -> concat hi/lo
    attn_kernel<<<dim3(BH, Nseq / 128), 256, 184320>>>();

    // output dense
    gemm_kernel<<<dim3(MT / 128, 4, 1), 256, 81920>>>(chi, clo, bd, out, 1);
}

// round 5
// speedup vs baseline: 3.2176x; 1.1416x over previous
#include <cuda_runtime.h>
#include <cuda_bf16.h>
#include <stdint.h>
#include <math.h>

// Problem constants
#define Bdim 8
#define Nseq 4096
#define Dmod 512
#define Hh   8
#define Rr   256
#define DP   64
#define BH   64          // Bdim*Hh
#define MT   32768       // Bdim*Nseq

// ---------------------------------------------------------------------------
// Scratch (module-static device memory)
// ---------------------------------------------------------------------------
__device__ __nv_bfloat16 g_xhi[(size_t)MT * Dmod];
__device__ __nv_bfloat16 g_xlo[(size_t)MT * Dmod];
__device__ __nv_bfloat16 g_whi[4 * Dmod * Dmod];   // [z][n][k] transposed
__device__ __nv_bfloat16 g_wlo[4 * Dmod * Dmod];
__device__ __nv_bfloat16 g_ehi[(size_t)Hh * Nseq * Rr];
__device__ __nv_bfloat16 g_elo[(size_t)Hh * Nseq * Rr];
__device__ __nv_bfloat16 g_fhi[(size_t)Hh * Nseq * Rr];
__device__ __nv_bfloat16 g_flo[(size_t)Hh * Nseq * Rr];
__device__ __nv_bfloat16 g_qhi[(size_t)BH * Nseq * DP];
__device__ __nv_bfloat16 g_qlo[(size_t)BH * Nseq * DP];
__device__ __nv_bfloat16 g_khi[(size_t)BH * Nseq * DP];
__device__ __nv_bfloat16 g_klo[(size_t)BH * Nseq * DP];
__device__ __nv_bfloat16 g_vhi[(size_t)BH * Nseq * DP];
__device__ __nv_bfloat16 g_vlo[(size_t)BH * Nseq * DP];
__device__ float         g_part[(size_t)8 * 1048576];   // [ef][ksplit][bh][256][64]
__device__ __nv_bfloat16 g_kphi[(size_t)BH * Rr * DP];
__device__ __nv_bfloat16 g_kplo[(size_t)BH * Rr * DP];
__device__ __nv_bfloat16 g_vphi[(size_t)BH * Rr * DP];
__device__ __nv_bfloat16 g_vplo[(size_t)BH * Rr * DP];
__device__ __nv_bfloat16 g_chi[(size_t)MT * Dmod];
__device__ __nv_bfloat16 g_clo[(size_t)MT * Dmod];

// ---------------------------------------------------------------------------
// PTX helpers (compute_103-safe)
// ---------------------------------------------------------------------------
__device__ __forceinline__ uint32_t smem_u32(const void* p) {
    uint32_t a;
    asm("{ .reg .u64 t; cvta.to.shared.u64 t, %1; cvt.u32.u64 %0, t; }" : "=r"(a) : "l"(p));
    return a;
}
__device__ __forceinline__ void cpa16(uint32_t dst, const void* src) {
    asm volatile("cp.async.cg.shared.global [%0], [%1], 16;" :: "r"(dst), "l"(src));
}
__device__ __forceinline__ void ldsm4(uint32_t& r0, uint32_t& r1, uint32_t& r2,
                                      uint32_t& r3, uint32_t addr) {
    asm volatile("ldmatrix.sync.aligned.m8n8.x4.shared.b16 {%0,%1,%2,%3}, [%4];"
                 : "=r"(r0), "=r"(r1), "=r"(r2), "=r"(r3) : "r"(addr));
}
__device__ __forceinline__ void ldsm4t(uint32_t& r0, uint32_t& r1, uint32_t& r2,
                                       uint32_t& r3, uint32_t addr) {
    asm volatile("ldmatrix.sync.aligned.m8n8.x4.trans.shared.b16 {%0,%1,%2,%3}, [%4];"
                 : "=r"(r0), "=r"(r1), "=r"(r2), "=r"(r3) : "r"(addr));
}
__device__ __forceinline__ void mma16816(float* c, uint32_t a0, uint32_t a1,
                                         uint32_t a2, uint32_t a3,
                                         uint32_t b0, uint32_t b1) {
    asm volatile(
        "mma.sync.aligned.m16n8k16.row.col.f32.bf16.bf16.f32 "
        "{%0,%1,%2,%3}, {%4,%5,%6,%7}, {%8,%9}, {%0,%1,%2,%3};"
        : "+f"(c[0]), "+f"(c[1]), "+f"(c[2]), "+f"(c[3])
        : "r"(a0), "r"(a1), "r"(a2), "r"(a3), "r"(b0), "r"(b1));
}
__device__ __forceinline__ uint32_t fsplit2(float a, float b, uint32_t& lo) {
    __nv_bfloat16 ha = __float2bfloat16(a), hb = __float2bfloat16(b);
    __nv_bfloat16 la = __float2bfloat16(a - __bfloat162float(ha));
    __nv_bfloat16 lb = __float2bfloat16(b - __bfloat162float(hb));
    __nv_bfloat162 H = __halves2bfloat162(ha, hb);
    __nv_bfloat162 L = __halves2bfloat162(la, lb);
    lo = *(uint32_t*)&L;
    return *(uint32_t*)&H;
}
// fast exp2 via degree-6 poly (rel err ~1.6e-5) — FMA pipe, no MUFU
__device__ __forceinline__ float fexp2(float x) {
    x = fmaxf(x, -120.f);
    float xi = floorf(x);
    float f = x - xi;
    float p = 1.54035304e-4f;
    p = fmaf(p, f, 1.33335581e-3f);
    p = fmaf(p, f, 9.61812911e-3f);
    p = fmaf(p, f, 5.55041087e-2f);
    p = fmaf(p, f, 2.40226507e-1f);
    p = fmaf(p, f, 6.93147181e-1f);
    p = fmaf(p, f, 1.0f);
    return p * __int_as_float(((int)xi + 127) << 23);
}

// ---------------------------------------------------------------------------
// split: fp32 -> (hi, lo) bf16
// ---------------------------------------------------------------------------
__global__ __launch_bounds__(256) void split_kernel(
    const float* __restrict__ in, __nv_bfloat16* __restrict__ hi,
    __nv_bfloat16* __restrict__ lo)
{
    size_t i = ((size_t)blockIdx.x * 256 + threadIdx.x) * 4;
    float4 v = *(const float4*)(in + i);
    uint32_t l0, l1;
    uint32_t h0 = fsplit2(v.x, v.y, l0);
    uint32_t h1 = fsplit2(v.z, v.w, l1);
    *(uint32_t*)(hi + i)     = h0;
    *(uint32_t*)(hi + i + 2) = h1;
    *(uint32_t*)(lo + i)     = l0;
    *(uint32_t*)(lo + i + 2) = l1;
}

// merged E/F split: grid (.x blocks, 2)
__global__ __launch_bounds__(256) void splitEF_kernel(
    const float* __restrict__ E, const float* __restrict__ F)
{
    const int ef = blockIdx.y;
    const float* in = ef ? F : E;
    __nv_bfloat16* hi = ef ? g_fhi : g_ehi;
    __nv_bfloat16* lo = ef ? g_flo : g_elo;
    size_t i = ((size_t)blockIdx.x * 256 + threadIdx.x) * 4;
    float4 v = *(const float4*)(in + i);
    uint32_t l0, l1;
    uint32_t h0 = fsplit2(v.x, v.y, l0);
    uint32_t h1 = fsplit2(v.z, v.w, l1);
    *(uint32_t*)(hi + i)     = h0;
    *(uint32_t*)(hi + i + 2) = h1;
    *(uint32_t*)(lo + i)     = l0;
    *(uint32_t*)(lo + i + 2) = l1;
}

// transpose + split weights: g_w{hi,lo}[z][n][k] = split(w_z[k][n])
__global__ __launch_bounds__(256) void convw_kernel(
    const float* __restrict__ wq, const float* __restrict__ wk,
    const float* __restrict__ wv, const float* __restrict__ wd)
{
    const int z = blockIdx.z;
    const float* w = (z == 0) ? wq : (z == 1) ? wk : (z == 2) ? wv : wd;
    __shared__ float tile[32][33];
    const int k0 = blockIdx.x * 32, n0 = blockIdx.y * 32;
    const int tx = threadIdx.x, ty = threadIdx.y;   // block (32, 8)
#pragma unroll
    for (int i = 0; i < 4; i++)
        tile[ty + i * 8][tx] = w[(size_t)(k0 + ty + i * 8) * Dmod + n0 + tx];
    __syncthreads();
#pragma unroll
    for (int i = 0; i < 4; i++) {
        float x = tile[tx][ty + i * 8];
        __nv_bfloat16 h = __float2bfloat16(x);
        size_t o = (size_t)z * Dmod * Dmod + (size_t)(n0 + ty + i * 8) * Dmod + k0 + tx;
        g_whi[o] = h;
        g_wlo[o] = __float2bfloat16(x - __bfloat162float(h));
    }
}

// ---------------------------------------------------------------------------
// mma.sync split-bf16 GEMM: C(128x128) = A(Mx512) @ W(512x512)
// Grid: (nVariants, 256) with x = z*4+col (mode 0) or col (mode 1), y = rowChunk.
// x-fastest wave order => all variants of one rowBase run concurrently =>
// A tiles served from L2 after one DRAM read.
// ---------------------------------------------------------------------------
__device__ __forceinline__ void issue_chunk(
    const __nv_bfloat16* __restrict__ Ahi, const __nv_bfloat16* __restrict__ Alo,
    const __nv_bfloat16* __restrict__ Bhi, const __nv_bfloat16* __restrict__ Blo,
    uint32_t sb, int stage, int c, int t, int rowBase, int colBase)
{
    const int k0 = c * 32;
#pragma unroll
    for (int u = 0; u < 2; u++) {
        int id = t + u * 256;
        int row = id >> 2, k8 = id & 3;
        size_t gA = (size_t)(rowBase + row) * Dmod + k0 + k8 * 8;
        size_t gB = (size_t)(colBase + row) * Dmod + k0 + k8 * 8;
        uint32_t so = sb + stage * 40960 + row * 80 + k8 * 16;
        cpa16(so + 0,     Ahi + gA);
        cpa16(so + 10240, Alo + gA);
        cpa16(so + 20480, Bhi + gB);
        cpa16(so + 30720, Blo + gB);
    }
    asm volatile("cp.async.commit_group;" ::: "memory");
}

__global__ __launch_bounds__(256) void gemm_kernel(
    const __nv_bfloat16* __restrict__ Ahi, const __nv_bfloat16* __restrict__ Alo,
    const float* __restrict__ bias, float* __restrict__ dOut, int mode)
{
    extern __shared__ __align__(128) char smx[];
    const uint32_t sb = smem_u32(smx);
    const int t = threadIdx.x;
    const int lane = t & 31, wid = t >> 5;
    const int warpM = wid & 3, warpN = wid >> 2;
    const int z   = (mode == 0) ? (blockIdx.x >> 2) : 3;
    const int col = (mode == 0) ? (blockIdx.x & 3) : blockIdx.x;
    const int rowBase = blockIdx.y * 128;
    const int colBase = col * 128;
    const __nv_bfloat16* Bhi = g_whi + (size_t)z * Dmod * Dmod;
    const __nv_bfloat16* Blo = g_wlo + (size_t)z * Dmod * Dmod;

    float acc[2][8][4];
#pragma unroll
    for (int mi = 0; mi < 2; mi++)
#pragma unroll
        for (int nf = 0; nf < 8; nf++)
#pragma unroll
            for (int j = 0; j < 4; j++) acc[mi][nf][j] = 0.f;

    issue_chunk(Ahi, Alo, Bhi, Blo, sb, 0, 0, t, rowBase, colBase);

    for (int c = 0; c < 16; c++) {
        if (c < 15) {
            issue_chunk(Ahi, Alo, Bhi, Blo, sb, (c + 1) & 1, c + 1, t, rowBase, colBase);
            asm volatile("cp.async.wait_group 1;" ::: "memory");
        } else {
            asm volatile("cp.async.wait_group 0;" ::: "memory");
        }
        __syncthreads();

        const uint32_t sA = sb + (c & 1) * 40960;
#pragma unroll
        for (int kk = 0; kk < 2; kk++) {
            // hoist all hi/lo fragments once, run 3 passes from registers
            uint32_t ahi[2][4], alo[2][4], bhi[16], blo[16];
#pragma unroll
            for (int mi = 0; mi < 2; mi++) {
                int row = warpM * 32 + mi * 16 + (lane & 15);
                int colk = kk * 16 + (lane >> 4) * 8;
                uint32_t ao = row * 80 + colk * 2;
                ldsm4(ahi[mi][0], ahi[mi][1], ahi[mi][2], ahi[mi][3], sA + ao);
                ldsm4(alo[mi][0], alo[mi][1], alo[mi][2], alo[mi][3], sA + 10240 + ao);
            }
#pragma unroll
            for (int g = 0; g < 4; g++) {
                int row = warpN * 64 + g * 16 + (lane & 7) + (lane >> 4) * 8;
                int colk = kk * 16 + ((lane >> 3) & 1) * 8;
                uint32_t bo = row * 80 + colk * 2;
                ldsm4(bhi[g * 4], bhi[g * 4 + 1], bhi[g * 4 + 2], bhi[g * 4 + 3],
                      sA + 20480 + bo);
                ldsm4(blo[g * 4], blo[g * 4 + 1], blo[g * 4 + 2], blo[g * 4 + 3],
                      sA + 30720 + bo);
            }
#pragma unroll
            for (int mi = 0; mi < 2; mi++)
#pragma unroll
                for (int nf = 0; nf < 8; nf++) {
                    int g = nf >> 1, j = nf & 1;
                    uint32_t b0 = bhi[g * 4 + j * 2], b1 = bhi[g * 4 + j * 2 + 1];
                    uint32_t l0 = blo[g * 4 + j * 2], l1 = blo[g * 4 + j * 2 + 1];
                    mma16816(acc[mi][nf], ahi[mi][0], ahi[mi][1], ahi[mi][2], ahi[mi][3], b0, b1);
                    mma16816(acc[mi][nf], ahi[mi][0], ahi[mi][1], ahi[mi][2], ahi[mi][3], l0, l1);
                    mma16816(acc[mi][nf], alo[mi][0], alo[mi][1], alo[mi][2], alo[mi][3], b0, b1);
                }
        }
        __syncthreads();
    }

    const int r0base = rowBase + warpM * 32 + (lane >> 2);
    if (mode == 0) {
        __nv_bfloat16* oh = (z == 0) ? g_qhi : (z == 1) ? g_khi : g_vhi;
        __nv_bfloat16* ol = (z == 0) ? g_qlo : (z == 1) ? g_klo : g_vlo;
        const int h = (colBase + warpN * 64) >> 6;
#pragma unroll
        for (int mi = 0; mi < 2; mi++) {
            int r0 = r0base + mi * 16;
            int bb = r0 >> 12, n = r0 & 4095;
            size_t rb0 = ((size_t)(bb * Hh + h) * Nseq + n) * DP;
            size_t rb1 = rb0 + 8 * DP;
#pragma unroll
            for (int nf = 0; nf < 8; nf++) {
                int d = nf * 8 + (lane & 3) * 2;
                uint32_t lo0, lo1;
                uint32_t hi0 = fsplit2(acc[mi][nf][0], acc[mi][nf][1], lo0);
                uint32_t hi1 = fsplit2(acc[mi][nf][2], acc[mi][nf][3], lo1);
                *(uint32_t*)(oh + rb0 + d) = hi0;
                *(uint32_t*)(ol + rb0 + d) = lo0;
                *(uint32_t*)(oh + rb1 + d) = hi1;
                *(uint32_t*)(ol + rb1 + d) = lo1;
            }
        }
    } else {
        const int col0 = colBase + warpN * 64;
#pragma unroll
        for (int mi = 0; mi < 2; mi++) {
            int r0 = r0base + mi * 16;
            float* p0 = dOut + (size_t)r0 * Dmod + col0;
            float* p1 = p0 + 8 * Dmod;
#pragma unroll
            for (int nf = 0; nf < 8; nf++) {
                int d = nf * 8 + (lane & 3) * 2;
                float2 bi = *(const float2*)(bias + col0 + d);
                *(float2*)(p0 + d) = make_float2(acc[mi][nf][0] + bi.x,
                                                 acc[mi][nf][1] + bi.y);
                *(float2*)(p1 + d) = make_float2(acc[mi][nf][2] + bi.x,
                                                 acc[mi][nf][3] + bi.y);
            }
        }
    }
}

// ---------------------------------------------------------------------------
// proj: kp/vp[r,d] = sum_n E/F[h,n,r] * k/v[bh,n,d] via mma (trans ldmatrix).
// ---------------------------------------------------------------------------
#define PEHI 0
#define PELO 16896
#define PKHI 33792
#define PKLO 38400
#define PSTG 43008

__global__ __launch_bounds__(256) void proj_kernel()
{
    extern __shared__ __align__(128) char smx[];
    const uint32_t sb = smem_u32(smx);
    const int t = threadIdx.x, lane = t & 31, wid = t >> 5;
    const int warpM = wid & 3, warpN = wid >> 2;   // r, d
    const int bh = blockIdx.x & 63, ef = blockIdx.x >> 6;
    const int ks = blockIdx.y;
    const int h = bh & 7;

    const __nv_bfloat16* Eh = (ef ? g_fhi : g_ehi) + (size_t)h * Nseq * Rr;
    const __nv_bfloat16* El = (ef ? g_flo : g_elo) + (size_t)h * Nseq * Rr;
    const __nv_bfloat16* Kh = (ef ? g_vhi : g_khi) + (size_t)bh * Nseq * DP;
    const __nv_bfloat16* Kl = (ef ? g_vlo : g_klo) + (size_t)bh * Nseq * DP;
    float* part = g_part + (((size_t)ef * 4 + ks) * 64 + bh) * 16384;

    const int nBase = ks * 1024;
    const int r0 = warpM * 64, d0 = warpN * 32;

    float acc[16][4];
#pragma unroll
    for (int i = 0; i < 16; i++)
#pragma unroll
        for (int j = 0; j < 4; j++) acc[i][j] = 0.f;

    auto issue = [&](int stage, int c) {
        const int n0 = nBase + c * 32;
        const uint32_t so = sb + stage * PSTG;
#pragma unroll
        for (int u = 0; u < 4; u++) {
            int id = u * 256 + t;
            int row = id >> 5, seg = id & 31;
            cpa16(so + PEHI + row * 528 + seg * 16, Eh + (size_t)(n0 + row) * Rr + seg * 8);
            cpa16(so + PELO + row * 528 + seg * 16, El + (size_t)(n0 + row) * Rr + seg * 8);
        }
        {
            int row = t >> 3, seg = t & 7;
            cpa16(so + PKHI + row * 144 + seg * 16, Kh + (size_t)(n0 + row) * DP + seg * 8);
            cpa16(so + PKLO + row * 144 + seg * 16, Kl + (size_t)(n0 + row) * DP + seg * 8);
        }
        asm volatile("cp.async.commit_group;" ::: "memory");
    };

    issue(0, 0);
    for (int c = 0; c < 32; c++) {
        if (c < 31) {
            issue((c + 1) & 1, c + 1);
            asm volatile("cp.async.wait_group 1;" ::: "memory");
        } else {
            asm volatile("cp.async.wait_group 0;" ::: "memory");
        }
        __syncthreads();

        const uint32_t st = sb + (c & 1) * PSTG;
#pragma unroll
        for (int kk = 0; kk < 2; kk++) {
            uint32_t ah[4][4], al[4][4];
            const int krA = kk * 16 + (lane & 7) + ((lane >> 4) & 1) * 8;
#pragma unroll
            for (int mf = 0; mf < 4; mf++) {
                uint32_t off = krA * 528 + (r0 + mf * 16 + ((lane >> 3) & 1) * 8) * 2;
                ldsm4t(ah[mf][0], ah[mf][1], ah[mf][2], ah[mf][3], st + PEHI + off);
                ldsm4t(al[mf][0], al[mf][1], al[mf][2], al[mf][3], st + PELO + off);
            }
            const int krB = kk * 16 + (lane & 7) + ((lane >> 3) & 1) * 8;
#pragma unroll
            for (int g2 = 0; g2 < 2; g2++) {
                uint32_t off = krB * 144 + (d0 + g2 * 16 + ((lane >> 4) & 1) * 8) * 2;
                uint32_t b0, b1, b2, b3, l0, l1, l2, l3;
                ldsm4t(b0, b1, b2, b3, st + PKHI + off);
                ldsm4t(l0, l1, l2, l3, st + PKLO + off);
#pragma unroll
                for (int mf = 0; mf < 4; mf++) {
                    float* c0 = acc[mf * 4 + g2 * 2];
                    float* c1 = acc[mf * 4 + g2 * 2 + 1];
                    mma16816(c0, ah[mf][0], ah[mf][1], ah[mf][2], ah[mf][3], b0, b1);
                    mma16816(c1, ah[mf][0], ah[mf][1], ah[mf][2], ah[mf][3], b2, b3);
                    mma16816(c0, ah[mf][0], ah[mf][1], ah[mf][2], ah[mf][3], l0, l1);
                    mma16816(c1, ah[mf][0], ah[mf][1], ah[mf][2], ah[mf][3], l2, l3);
                    mma16816(c0, al[mf][0], al[mf][1], al[mf][2], al[mf][3], b0, b1);
                    mma16816(c1, al[mf][0], al[mf][1], al[mf][2], al[mf][3], b2, b3);
                }
            }
        }
        __syncthreads();
    }

#pragma unroll
    for (int mf = 0; mf < 4; mf++) {
        int r = r0 + mf * 16 + (lane >> 2);
#pragma unroll
        for (int f = 0; f < 4; f++) {
            int d = d0 + f * 8 + (lane & 3) * 2;
            *(float2*)(part + r * 64 + d) =
                make_float2(acc[mf * 4 + f][0], acc[mf * 4 + f][1]);
            *(float2*)(part + (r + 8) * 64 + d) =
                make_float2(acc[mf * 4 + f][2], acc[mf * 4 + f][3]);
        }
    }
}

// reduce 4 K-split partials -> split to bf16 hi/lo kp/vp. grid (1024, 2).
__global__ __launch_bounds__(256) void reduce_kernel()
{
    const int ef = blockIdx.y;
    size_t base = ((size_t)blockIdx.x * 256 + threadIdx.x) * 4;
    const float* p = g_part + (size_t)ef * 4194304 + base;
    float4 s0 = *(const float4*)(p);
    float4 s1 = *(const float4*)(p + 1048576);
    float4 s2 = *(const float4*)(p + 2097152);
    float4 s3 = *(const float4*)(p + 3145728);
    float a = s0.x + s1.x + s2.x + s3.x;
    float b = s0.y + s1.y + s2.y + s3.y;
    float c = s0.z + s1.z + s2.z + s3.z;
    float d = s0.w + s1.w + s2.w + s3.w;
    __nv_bfloat16* hi = ef ? g_vphi : g_kphi;
    __nv_bfloat16* lo = ef ? g_vplo : g_kplo;
    uint32_t l0, l1;
    uint32_t h0 = fsplit2(a, b, l0);
    uint32_t h1 = fsplit2(c, d, l1);
    *(uint32_t*)(hi + base)     = h0;
    *(uint32_t*)(hi + base + 2) = h1;
    *(uint32_t*)(lo + base)     = l0;
    *(uint32_t*)(lo + base + 2) = l1;
}

// ---------------------------------------------------------------------------
// attn: per block one (b,h) + 128 q rows. All-mma, register softmax, poly exp2.
// ---------------------------------------------------------------------------
#define AQHI 0
#define AQLO 18432
#define AKPHI 36864
#define AKPLO 73728
#define AVPHI 110592
#define AVPLO 147456

__global__ __launch_bounds__(256) void attn_kernel()
{
    extern __shared__ __align__(128) char smx[];
    const uint32_t sb = smem_u32(smx);
    const int t = threadIdx.x, lane = t & 31, w = t >> 5;
    const int bh = blockIdx.x, tile = blockIdx.y;

    const __nv_bfloat16* qh = g_qhi + ((size_t)bh * Nseq + tile * 128) * DP;
    const __nv_bfloat16* ql = g_qlo + ((size_t)bh * Nseq + tile * 128) * DP;
    const __nv_bfloat16* kh = g_kphi + (size_t)bh * Rr * DP;
    const __nv_bfloat16* kl = g_kplo + (size_t)bh * Rr * DP;
    const __nv_bfloat16* vh = g_vphi + (size_t)bh * Rr * DP;
    const __nv_bfloat16* vl = g_vplo + (size_t)bh * Rr * DP;

#pragma unroll
    for (int u = 0; u < 4; u++) {
        int id = u * 256 + t, row = id >> 3, seg = id & 7;
        cpa16(sb + AQHI + row * 144 + seg * 16, qh + row * 64 + seg * 8);
        cpa16(sb + AQLO + row * 144 + seg * 16, ql + row * 64 + seg * 8);
    }
#pragma unroll
    for (int u = 0; u < 8; u++) {
        int id = u * 256 + t, row = id >> 3, seg = id & 7;
        cpa16(sb + AKPHI + row * 144 + seg * 16, kh + row * 64 + seg * 8);
        cpa16(sb + AKPLO + row * 144 + seg * 16, kl + row * 64 + seg * 8);
        cpa16(sb + AVPHI + row * 144 + seg * 16, vh + row * 64 + seg * 8);
        cpa16(sb + AVPLO + row * 144 + seg * 16, vl + row * 64 + seg * 8);
    }
    asm volatile("cp.async.commit_group;" ::: "memory");
    asm volatile("cp.async.wait_group 0;" ::: "memory");
    __syncthreads();

    const int m0 = w * 16;
    float c[32][4];
#pragma unroll
    for (int i = 0; i < 32; i++)
#pragma unroll
        for (int j = 0; j < 4; j++) c[i][j] = 0.f;

#pragma unroll
    for (int kk = 0; kk < 4; kk++) {
        uint32_t ah0, ah1, ah2, ah3, al0, al1, al2, al3;
        {
            uint32_t ar = (m0 + (lane & 15)) * 144 + (kk * 16 + (lane >> 4) * 8) * 2;
            ldsm4(ah0, ah1, ah2, ah3, sb + AQHI + ar);
            ldsm4(al0, al1, al2, al3, sb + AQLO + ar);
        }
#pragma unroll
        for (int nb = 0; nb < 16; nb++) {
            uint32_t br = (nb * 16 + (lane & 7) + ((lane >> 4) & 1) * 8) * 144
                        + (kk * 16 + ((lane >> 3) & 1) * 8) * 2;
            uint32_t b0, b1, b2, b3, l0, l1, l2, l3;
            ldsm4(b0, b1, b2, b3, sb + AKPHI + br);
            ldsm4(l0, l1, l2, l3, sb + AKPLO + br);
            mma16816(c[2 * nb],     ah0, ah1, ah2, ah3, b0, b1);
            mma16816(c[2 * nb + 1], ah0, ah1, ah2, ah3, b2, b3);
            mma16816(c[2 * nb],     ah0, ah1, ah2, ah3, l0, l1);
            mma16816(c[2 * nb + 1], ah0, ah1, ah2, ah3, l2, l3);
            mma16816(c[2 * nb],     al0, al1, al2, al3, b0, b1);
            mma16816(c[2 * nb + 1], al0, al1, al2, al3, b2, b3);
        }
    }

    const float C = 0.125f * 1.4426950408889634f;
    float mx0 = -1e30f, mx1 = -1e30f;
#pragma unroll
    for (int f = 0; f < 32; f++) {
        mx0 = fmaxf(mx0, fmaxf(c[f][0], c[f][1]));
        mx1 = fmaxf(mx1, fmaxf(c[f][2], c[f][3]));
    }
    mx0 = fmaxf(mx0, __shfl_xor_sync(0xffffffffu, mx0, 1));
    mx0 = fmaxf(mx0, __shfl_xor_sync(0xffffffffu, mx0, 2));
    mx1 = fmaxf(mx1, __shfl_xor_sync(0xffffffffu, mx1, 1));
    mx1 = fmaxf(mx1, __shfl_xor_sync(0xffffffffu, mx1, 2));
    float s0 = 0.f, s1 = 0.f;
#pragma unroll
    for (int f = 0; f < 32; f++) {
        c[f][0] = fexp2((c[f][0] - mx0) * C);
        c[f][1] = fexp2((c[f][1] - mx0) * C);
        c[f][2] = fexp2((c[f][2] - mx1) * C);
        c[f][3] = fexp2((c[f][3] - mx1) * C);
        s0 += c[f][0] + c[f][1];
        s1 += c[f][2] + c[f][3];
    }
    s0 += __shfl_xor_sync(0xffffffffu, s0, 1);
    s0 += __shfl_xor_sync(0xffffffffu, s0, 2);
    s1 += __shfl_xor_sync(0xffffffffu, s1, 1);
    s1 += __shfl_xor_sync(0xffffffffu, s1, 2);
    const float inv0 = 1.f / s0, inv1 = 1.f / s1;

    uint32_t phi[64], plo[64];
#pragma unroll
    for (int f = 0; f < 32; f++) {
        float p0 = c[f][0] * inv0, p1 = c[f][1] * inv0;
        float p2 = c[f][2] * inv1, p3 = c[f][3] * inv1;
        int base = (f >> 1) * 4 + (f & 1) * 2;
        uint32_t lo0, lo1;
        phi[base]     = fsplit2(p0, p1, lo0);
        phi[base + 1] = fsplit2(p2, p3, lo1);
        plo[base]     = lo0;
        plo[base + 1] = lo1;
    }

    float o[8][4];
#pragma unroll
    for (int i = 0; i < 8; i++)
#pragma unroll
        for (int j = 0; j < 4; j++) o[i][j] = 0.f;

#pragma unroll
    for (int ks = 0; ks < 16; ks++) {
        uint32_t A0 = phi[ks * 4], A1 = phi[ks * 4 + 1];
        uint32_t A2 = phi[ks * 4 + 2], A3 = phi[ks * 4 + 3];
        uint32_t L0 = plo[ks * 4], L1 = plo[ks * 4 + 1];
        uint32_t L2 = plo[ks * 4 + 2], L3 = plo[ks * 4 + 3];
        const int krB = ks * 16 + (lane & 7) + ((lane >> 3) & 1) * 8;
#pragma unroll
        for (int g2 = 0; g2 < 4; g2++) {
            uint32_t off = krB * 144 + (g2 * 16 + ((lane >> 4) & 1) * 8) * 2;
            uint32_t b0, b1, b2, b3, l0, l1, l2, l3;
            ldsm4t(b0, b1, b2, b3, sb + AVPHI + off);
            ldsm4t(l0, l1, l2, l3, sb + AVPLO + off);
            mma16816(o[g2 * 2],     A0, A1, A2, A3, b0, b1);
            mma16816(o[g2 * 2 + 1], A0, A1, A2, A3, b2, b3);
            mma16816(o[g2 * 2],     A0, A1, A2, A3, l0, l1);
            mma16816(o[g2 * 2 + 1], A0, A1, A2, A3, l2, l3);
            mma16816(o[g2 * 2],     L0, L1, L2, L3, b0, b1);
            mma16816(o[g2 * 2 + 1], L0, L1, L2, L3, b2, b3);
        }
    }

    const int n0 = tile * 128 + m0 + (lane >> 2);
    const int b = bh >> 3, h = bh & 7;
#pragma unroll
    for (int f = 0; f < 8; f++) {
        int d = f * 8 + (lane & 3) * 2;
        size_t i0 = (size_t)(b * Nseq + n0) * Dmod + h * 64 + d;
        size_t i1 = i0 + (size_t)8 * Dmod;
        uint32_t lo0, lo1;
        uint32_t hi0 = fsplit2(o[f][0], o[f][1], lo0);
        uint32_t hi1 = fsplit2(o[f][2], o[f][3], lo1);
        *(uint32_t*)(g_chi + i0) = hi0;
        *(uint32_t*)(g_clo + i0) = lo0;
        *(uint32_t*)(g_chi + i1) = hi1;
        *(uint32_t*)(g_clo + i1) = lo1;
    }
}

// ---------------------------------------------------------------------------
extern "C" void kernel_launch(void* const* d_in, const int* in_sizes, int n_in,
                              void* d_out, int out_size)
{
    const float* x  = (const float*)d_in[0];
    const float* wq = (const float*)d_in[1];
    const float* wk = (const float*)d_in[2];
    const float* wv = (const float*)d_in[3];
    const float* E  = (const float*)d_in[4];
    const float* F  = (const float*)d_in[5];
    const float* wd = (const float*)d_in[6];
    const float* bd = (const float*)d_in[7];
    float* out = (float*)d_out;

    __nv_bfloat16 *xhi, *xlo, *chi, *clo;
    cudaGetSymbolAddress((void**)&xhi, g_xhi);
    cudaGetSymbolAddress((void**)&xlo, g_xlo);
    cudaGetSymbolAddress((void**)&chi, g_chi);
    cudaGetSymbolAddress((void**)&clo, g_clo);

    cudaFuncSetAttribute(gemm_kernel,
                         cudaFuncAttributeMaxDynamicSharedMemorySize, 81920);
    cudaFuncSetAttribute(proj_kernel,
                         cudaFuncAttributeMaxDynamicSharedMemorySize, 86016);
    cudaFuncSetAttribute(attn_kernel,
                         cudaFuncAttributeMaxDynamicSharedMemorySize, 184320);

    // splits
    split_kernel<<<(MT * Dmod) / 1024, 256>>>(x, xhi, xlo);
    splitEF_kernel<<<dim3((Hh * Nseq * Rr) / 1024, 2), 256>>>(E, F);
    convw_kernel<<<dim3(16, 16, 4), dim3(32, 8)>>>(wq, wk, wv, wd);

    // QKV -> bf16 hi/lo q,k,v (grid: x = variant, y = rowChunk for L2 A-reuse)
    gemm_kernel<<<dim3(12, MT / 128), 256, 81920>>>(xhi, xlo, nullptr, nullptr, 0);

    // low-rank projections -> partials -> kp/vp hi/lo
    proj_kernel<<<dim3(128, 4), 256, 86016>>>();
    reduce_kernel<<<dim3(1024, 2), 256>>>();

    // fused attention -> concat hi/lo
    attn_kernel<<<dim3(BH, Nseq / 128), 256, 184320>>>();

    // output dense
    gemm_kernel<<<dim3(4, MT / 128), 256, 81920>>>(chi, clo, bd, out, 1);
}